// round 1
// baseline (speedup 1.0000x reference)
#include <cuda_runtime.h>
#include <cstddef>

#define NN 50000
#define NE 800000
#define DIN 128
#define DHID 512
#define DOUT 256

// Scratch (device globals — no runtime allocation)
__device__ float g_h1[(size_t)NN * DIN];      // x + agg          (25.6 MB)
__device__ float g_hmid[(size_t)NN * DHID];   // after MLP layer1 (102.4 MB)
__device__ float g_h2[(size_t)NN * DOUT];     // after layer2+act (51.2 MB)
__device__ float g_sum[DOUT];
__device__ float g_sumsq[DOUT];
__device__ float g_scale[DOUT];
__device__ float g_shift[DOUT];

// ---------------------------------------------------------------------------
// 1) init: g_h1 = x (GIN eps=0 -> h = x + agg), zero BN stat accumulators
// ---------------------------------------------------------------------------
__global__ void k_init(const float* __restrict__ x) {
    int i = blockIdx.x * blockDim.x + threadIdx.x;
    const int n4 = NN * DIN / 4;
    if (i < n4) {
        reinterpret_cast<float4*>(g_h1)[i] =
            reinterpret_cast<const float4*>(x)[i];
    }
    if (blockIdx.x == 0 && threadIdx.x < DOUT) {
        g_sum[threadIdx.x] = 0.0f;
        g_sumsq[threadIdx.x] = 0.0f;
    }
}

// ---------------------------------------------------------------------------
// 2) scatter: g_h1[dst] += x[src]  (one warp per edge, float4 vector atomics)
// ---------------------------------------------------------------------------
__global__ void k_scatter(const float* __restrict__ x,
                          const int* __restrict__ ei) {
    int t = blockIdx.x * blockDim.x + threadIdx.x;
    if (t >= NE * 32) return;
    int e = t >> 5;
    int lane = t & 31;
    int src = ei[e];
    int dst = ei[NE + e];
    float4 v = reinterpret_cast<const float4*>(x + (size_t)src * DIN)[lane];
    float* p = g_h1 + (size_t)dst * DIN + lane * 4;
    asm volatile("red.global.add.v4.f32 [%0], {%1,%2,%3,%4};"
                 :: "l"(p), "f"(v.x), "f"(v.y), "f"(v.z), "f"(v.w)
                 : "memory");
}

// ---------------------------------------------------------------------------
// 3) fp32 GEMM + bias + LeakyReLU:  C[M,N] = lrelu(A[M,K] @ B[K,N] + bias)
//    128x128 tile, BK=16, 256 threads, 8x8 microtile per thread
// ---------------------------------------------------------------------------
__global__ __launch_bounds__(256)
void k_gemm_lrelu(const float* __restrict__ A, const float* __restrict__ B,
                  const float* __restrict__ bias, float* __restrict__ C,
                  int M, int N, int K) {
    constexpr int BM = 128, BN = 128, BK = 16;
    __shared__ float As[BK][BM];   // transposed: As[k][m]
    __shared__ float Bs[BK][BN];

    const int tid = threadIdx.x;
    const int tx = tid & 15;       // 0..15 (cols)
    const int ty = tid >> 4;       // 0..15 (rows)
    const int m0 = blockIdx.y * BM;
    const int n0 = blockIdx.x * BN;

    float acc[8][8] = {};

    for (int k0 = 0; k0 < K; k0 += BK) {
        // Load A tile: 128 rows x 16 k, 512 float4 by 256 threads
        #pragma unroll
        for (int i = 0; i < 2; i++) {
            int f = tid + i * 256;
            int m = f >> 2;              // 0..127
            int kg = (f & 3) * 4;        // 0,4,8,12
            float4 va = make_float4(0.f, 0.f, 0.f, 0.f);
            int gm = m0 + m;
            if (gm < M)
                va = *reinterpret_cast<const float4*>(A + (size_t)gm * K + k0 + kg);
            As[kg + 0][m] = va.x;
            As[kg + 1][m] = va.y;
            As[kg + 2][m] = va.z;
            As[kg + 3][m] = va.w;
        }
        // Load B tile: 16 k x 128 n (N is always a multiple of 128 here)
        #pragma unroll
        for (int i = 0; i < 2; i++) {
            int f = tid + i * 256;
            int kk = f >> 5;             // 0..15
            int nc = (f & 31) * 4;       // 0..124
            *reinterpret_cast<float4*>(&Bs[kk][nc]) =
                *reinterpret_cast<const float4*>(B + (size_t)(k0 + kk) * N + n0 + nc);
        }
        __syncthreads();

        #pragma unroll
        for (int k = 0; k < BK; k++) {
            float a[8], b[8];
            *reinterpret_cast<float4*>(&a[0]) = *reinterpret_cast<float4*>(&As[k][ty * 8]);
            *reinterpret_cast<float4*>(&a[4]) = *reinterpret_cast<float4*>(&As[k][ty * 8 + 4]);
            *reinterpret_cast<float4*>(&b[0]) = *reinterpret_cast<float4*>(&Bs[k][tx * 8]);
            *reinterpret_cast<float4*>(&b[4]) = *reinterpret_cast<float4*>(&Bs[k][tx * 8 + 4]);
            #pragma unroll
            for (int i = 0; i < 8; i++)
                #pragma unroll
                for (int j = 0; j < 8; j++)
                    acc[i][j] += a[i] * b[j];
        }
        __syncthreads();
    }

    // Epilogue: bias + leaky relu
    #pragma unroll
    for (int i = 0; i < 8; i++) {
        int gm = m0 + ty * 8 + i;
        if (gm >= M) break;
        #pragma unroll
        for (int j = 0; j < 8; j += 4) {
            int gn = n0 + tx * 8 + j;
            float4 v;
            v.x = acc[i][j + 0] + bias[gn + 0];
            v.y = acc[i][j + 1] + bias[gn + 1];
            v.z = acc[i][j + 2] + bias[gn + 2];
            v.w = acc[i][j + 3] + bias[gn + 3];
            v.x = v.x > 0.f ? v.x : 0.01f * v.x;
            v.y = v.y > 0.f ? v.y : 0.01f * v.y;
            v.z = v.z > 0.f ? v.z : 0.01f * v.z;
            v.w = v.w > 0.f ? v.w : 0.01f * v.w;
            *reinterpret_cast<float4*>(C + (size_t)gm * N + gn) = v;
        }
    }
}

// ---------------------------------------------------------------------------
// 4) BN column statistics: per-block register accumulation + spread atomics
// ---------------------------------------------------------------------------
__global__ void k_colsum() {
    int col = threadIdx.x;   // 256 threads, one column each
    float s = 0.f, ss = 0.f;
    for (int r = blockIdx.x; r < NN; r += gridDim.x) {
        float v = g_h2[(size_t)r * DOUT + col];
        s += v;
        ss += v * v;
    }
    atomicAdd(&g_sum[col], s);
    atomicAdd(&g_sumsq[col], ss);
}

// ---------------------------------------------------------------------------
// 5) finalize BN params: scale = gamma*rstd, shift = beta - mean*gamma*rstd
// ---------------------------------------------------------------------------
__global__ void k_bn_finalize(const float* __restrict__ gamma,
                              const float* __restrict__ beta) {
    int c = threadIdx.x;
    float invn = 1.0f / (float)NN;
    float mean = g_sum[c] * invn;
    float var = g_sumsq[c] * invn - mean * mean;
    float rstd = rsqrtf(var + 1e-5f);
    float sc = gamma[c] * rstd;
    g_scale[c] = sc;
    g_shift[c] = beta[c] - mean * sc;
}

// ---------------------------------------------------------------------------
// 6) normalize: out = h2 * scale + shift
// ---------------------------------------------------------------------------
__global__ void k_normalize(float* __restrict__ out) {
    int i = blockIdx.x * blockDim.x + threadIdx.x;
    const int n4 = NN * DOUT / 4;
    if (i >= n4) return;
    int c4 = i & (DOUT / 4 - 1);   // column group (DOUT/4 = 64)
    float4 v = reinterpret_cast<const float4*>(g_h2)[i];
    float4 sc = reinterpret_cast<const float4*>(g_scale)[c4];
    float4 sh = reinterpret_cast<const float4*>(g_shift)[c4];
    v.x = v.x * sc.x + sh.x;
    v.y = v.y * sc.y + sh.y;
    v.z = v.z * sc.z + sh.z;
    v.w = v.w * sc.w + sh.w;
    reinterpret_cast<float4*>(out)[i] = v;
}

// ---------------------------------------------------------------------------
extern "C" void kernel_launch(void* const* d_in, const int* in_sizes, int n_in,
                              void* d_out, int out_size) {
    const float* x     = (const float*)d_in[0];
    const int*   ei    = (const int*)d_in[1];
    const float* W1    = (const float*)d_in[2];
    const float* b1    = (const float*)d_in[3];
    const float* W2    = (const float*)d_in[4];
    const float* b2    = (const float*)d_in[5];
    const float* gamma = (const float*)d_in[6];
    const float* beta  = (const float*)d_in[7];
    float* out = (float*)d_out;

    float* h1   = nullptr;
    float* hmid = nullptr;
    float* h2   = nullptr;
    cudaGetSymbolAddress((void**)&h1,   g_h1);
    cudaGetSymbolAddress((void**)&hmid, g_hmid);
    cudaGetSymbolAddress((void**)&h2,   g_h2);

    // 1) h1 = x, zero stats
    {
        int n4 = NN * DIN / 4;
        k_init<<<(n4 + 255) / 256, 256>>>(x);
    }
    // 2) scatter-add
    {
        long long tot = (long long)NE * 32;
        int blocks = (int)((tot + 255) / 256);
        k_scatter<<<blocks, 256>>>(x, ei);
    }
    // 3) GEMM1: hmid = lrelu(h1 @ W1 + b1)   [50000x128]@[128x512]
    {
        dim3 grid(DHID / 128, (NN + 127) / 128);
        k_gemm_lrelu<<<grid, 256>>>(h1, W1, b1, hmid, NN, DHID, DIN);
    }
    // 4) GEMM2: h2 = lrelu(hmid @ W2 + b2)   [50000x512]@[512x256]
    {
        dim3 grid(DOUT / 128, (NN + 127) / 128);
        k_gemm_lrelu<<<grid, 256>>>(hmid, W2, b2, h2, NN, DOUT, DHID);
    }
    // 5) BN stats
    k_colsum<<<512, DOUT>>>();
    k_bn_finalize<<<1, DOUT>>>(gamma, beta);
    // 6) normalize -> out
    {
        int n4 = NN * DOUT / 4;
        k_normalize<<<(n4 + 255) / 256, 256>>>(out);
    }
}

// round 3
// speedup vs baseline: 1.5184x; 1.5184x over previous
#include <cuda_runtime.h>
#include <cuda_fp16.h>
#include <cstdint>
#include <cstddef>

#define NN 50000
#define NE 800000
#define DIN 128
#define DHID 512
#define DOUT 256

// ---------------------------------------------------------------------------
// Scratch (device globals — no runtime allocation)
// ---------------------------------------------------------------------------
__device__ float g_h1[(size_t)NN * DIN];         // x + agg (fp32)
__device__ __half g_xhi[(size_t)NN * DIN];       // h1 split hi
__device__ __half g_xlo[(size_t)NN * DIN];       // h1 split lo (*2048)
__device__ __half g_mhi[(size_t)NN * DHID];      // hmid hi
__device__ __half g_mlo[(size_t)NN * DHID];      // hmid lo (*2048)
__device__ float g_h2[(size_t)NN * DOUT];        // after layer2+act (fp32)
__device__ __half g_w1hi[(size_t)DHID * DIN];    // W1^T hi  [N][K]
__device__ __half g_w1lo[(size_t)DHID * DIN];
__device__ __half g_w2hi[(size_t)DOUT * DHID];   // W2^T hi
__device__ __half g_w2lo[(size_t)DOUT * DHID];
__device__ float g_sum[DOUT];
__device__ float g_sumsq[DOUT];
__device__ float g_scale[DOUT];
__device__ float g_shift[DOUT];

// ---------------------------------------------------------------------------
// PTX helpers (compute_100-safe: mma.sync / ldmatrix / cp.async)
// ---------------------------------------------------------------------------
__device__ __forceinline__ uint32_t smem_u32(const void* p) {
    uint32_t a;
    asm("{ .reg .u64 t; cvta.to.shared.u64 t, %1; cvt.u32.u64 %0, t; }"
        : "=r"(a) : "l"(p));
    return a;
}

__device__ __forceinline__ void cp_async16(uint32_t dst, const void* src, bool pred) {
    int sz = pred ? 16 : 0;
    asm volatile("cp.async.cg.shared.global [%0], [%1], 16, %2;"
                 :: "r"(dst), "l"(src), "r"(sz));
}
__device__ __forceinline__ void cp_commit() {
    asm volatile("cp.async.commit_group;" ::: "memory");
}
__device__ __forceinline__ void cp_wait0() {
    asm volatile("cp.async.wait_group 0;" ::: "memory");
}

__device__ __forceinline__ void ldsm_x4(uint32_t* r, uint32_t addr) {
    asm volatile("ldmatrix.sync.aligned.m8n8.x4.shared.b16 {%0,%1,%2,%3}, [%4];"
                 : "=r"(r[0]), "=r"(r[1]), "=r"(r[2]), "=r"(r[3]) : "r"(addr));
}

__device__ __forceinline__ void hmma(float* c, const uint32_t* a, const uint32_t* b) {
    asm volatile(
        "mma.sync.aligned.m16n8k16.row.col.f32.f16.f16.f32 "
        "{%0,%1,%2,%3}, {%4,%5,%6,%7}, {%8,%9}, {%0,%1,%2,%3};"
        : "+f"(c[0]), "+f"(c[1]), "+f"(c[2]), "+f"(c[3])
        : "r"(a[0]), "r"(a[1]), "r"(a[2]), "r"(a[3]), "r"(b[0]), "r"(b[1]));
}

// ---------------------------------------------------------------------------
// 1) init: g_h1 = x ; zero BN accumulators
// ---------------------------------------------------------------------------
__global__ void k_init(const float* __restrict__ x) {
    int i = blockIdx.x * blockDim.x + threadIdx.x;
    const int n4 = NN * DIN / 4;
    if (i < n4)
        reinterpret_cast<float4*>(g_h1)[i] = reinterpret_cast<const float4*>(x)[i];
    if (blockIdx.x == 0 && threadIdx.x < DOUT) {
        g_sum[threadIdx.x] = 0.0f;
        g_sumsq[threadIdx.x] = 0.0f;
    }
}

// ---------------------------------------------------------------------------
// 2) scatter: g_h1[dst] += x[src] via red.global.add.v4.f32 (1 warp per edge)
// ---------------------------------------------------------------------------
__global__ void k_scatter(const float* __restrict__ x, const int* __restrict__ ei) {
    int t = blockIdx.x * blockDim.x + threadIdx.x;
    if (t >= NE * 32) return;
    int e = t >> 5;
    int lane = t & 31;
    int src = ei[e];
    int dst = ei[NE + e];
    float4 v = reinterpret_cast<const float4*>(x + (size_t)src * DIN)[lane];
    float* p = g_h1 + (size_t)dst * DIN + lane * 4;
    asm volatile("red.global.add.v4.f32 [%0], {%1,%2,%3,%4};"
                 :: "l"(p), "f"(v.x), "f"(v.y), "f"(v.z), "f"(v.w) : "memory");
}

// ---------------------------------------------------------------------------
// 3) split g_h1 (fp32) -> hi/lo fp16 (lo scaled by 2048)
// ---------------------------------------------------------------------------
__global__ void k_split_h1() {
    int i = blockIdx.x * blockDim.x + threadIdx.x;
    if (i >= NN * DIN) return;
    float v = g_h1[i];
    __half h = __float2half_rn(v);
    g_xhi[i] = h;
    g_xlo[i] = __float2half_rn((v - __half2float(h)) * 2048.0f);
}

// ---------------------------------------------------------------------------
// 4) W [K,N] row-major -> W^T [N,K] hi/lo fp16
// ---------------------------------------------------------------------------
__global__ void k_prep_w(const float* __restrict__ W, __half* __restrict__ hi,
                         __half* __restrict__ lo, int K, int N) {
    int i = blockIdx.x * blockDim.x + threadIdx.x;
    if (i >= K * N) return;
    int n = i / K, k = i % K;
    float v = W[(size_t)k * N + n];
    __half h = __float2half_rn(v);
    hi[i] = h;
    lo[i] = __float2half_rn((v - __half2float(h)) * 2048.0f);
}

// ---------------------------------------------------------------------------
// 5) HMMA GEMM:  C[M,N] = lrelu(A @ B^T + bias), split-fp16 3-term
//    CTA tile 128x128, BK=32, 8 warps (warp tile 32x64), double-buffered
//    cp.async. A: [M][K] fp16 hi/lo.  B: [N][K] fp16 hi/lo (i.e. W^T).
// ---------------------------------------------------------------------------
#define ROWB 80                      // padded smem row stride (bytes) for 64B of data
#define MATB (128 * ROWB)            // one 128-row tile matrix = 10240 B
#define STAGEB (4 * MATB)            // Ahi,Alo,Bhi,Blo = 40960 B
#define GEMM_SMEM (2 * STAGEB)       // 81920 B

template <bool HALF_OUT>
__global__ void __launch_bounds__(256, 1)
k_gemm_mma(const __half* __restrict__ Ahi, const __half* __restrict__ Alo,
           const __half* __restrict__ Bhi, const __half* __restrict__ Blo,
           const float* __restrict__ bias,
           __half* __restrict__ Chi, __half* __restrict__ Clo,
           float* __restrict__ Cf,
           int M, int K, int ldc) {
    extern __shared__ char smem[];
    const uint32_t sb = smem_u32(smem);
    const int tid = threadIdx.x;
    const int wid = tid >> 5;
    const int lane = tid & 31;
    const int warp_m = wid & 3;      // 4 m-groups of 32 rows
    const int warp_n = wid >> 2;     // 2 n-groups of 64 cols
    const int m0 = blockIdx.y * 128;
    const int n0 = blockIdx.x * 128;

    float acc0[2][8][4];
    float acc1[2][8][4];
    #pragma unroll
    for (int a = 0; a < 2; a++)
        #pragma unroll
        for (int b = 0; b < 8; b++)
            #pragma unroll
            for (int c = 0; c < 4; c++) { acc0[a][b][c] = 0.f; acc1[a][b][c] = 0.f; }

    const int nchunks = K >> 5;

    // --- async loader for one chunk into stage s ---
    auto load_chunk = [&](int ch, int s) {
        const int k0 = ch << 5;
        const uint32_t stg = sb + s * STAGEB;
        #pragma unroll
        for (int it = 0; it < 2; it++) {
            int idx = tid + it * 256;          // 0..511
            int row = idx >> 2;                // 0..127
            int c = idx & 3;                   // 16B chunk
            uint32_t soff = (uint32_t)(row * ROWB + c * 16);
            int gmr = m0 + row;
            bool okA = gmr < M;
            const __half* pa = Ahi + (size_t)gmr * K + k0 + c * 8;
            const __half* pl = Alo + (size_t)gmr * K + k0 + c * 8;
            cp_async16(stg + 0 * MATB + soff, pa, okA);
            cp_async16(stg + 1 * MATB + soff, pl, okA);
            int gnr = n0 + row;                // N always multiple of 128
            const __half* pb = Bhi + (size_t)gnr * K + k0 + c * 8;
            const __half* pq = Blo + (size_t)gnr * K + k0 + c * 8;
            cp_async16(stg + 2 * MATB + soff, pb, true);
            cp_async16(stg + 3 * MATB + soff, pq, true);
        }
        cp_commit();
    };

    load_chunk(0, 0);
    cp_wait0();
    __syncthreads();

    for (int ch = 0; ch < nchunks; ch++) {
        const int s = ch & 1;
        if (ch + 1 < nchunks) load_chunk(ch + 1, s ^ 1);

        const uint32_t stg = sb + s * STAGEB;
        const uint32_t lrow = (uint32_t)(lane & 15);
        const uint32_t lchk = (uint32_t)(lane >> 4);

        #pragma unroll
        for (int ks = 0; ks < 2; ks++) {
            uint32_t a_hi[2][4], a_lo[2][4];
            #pragma unroll
            for (int mt = 0; mt < 2; mt++) {
                uint32_t r = (uint32_t)(warp_m * 32 + mt * 16) + lrow;
                uint32_t addr = stg + r * ROWB + lchk * 16 + ks * 32;
                ldsm_x4(a_hi[mt], addr + 0 * MATB);
                ldsm_x4(a_lo[mt], addr + 1 * MATB);
            }
            #pragma unroll
            for (int np = 0; np < 4; np++) {
                uint32_t bh[4], bl[4];
                uint32_t r = (uint32_t)(warp_n * 64 + np * 16) + lrow;
                uint32_t addr = stg + r * ROWB + lchk * 16 + ks * 32;
                ldsm_x4(bh, addr + 2 * MATB);
                ldsm_x4(bl, addr + 3 * MATB);
                uint32_t b0h[2] = {bh[0], bh[2]}, b1h[2] = {bh[1], bh[3]};
                uint32_t b0l[2] = {bl[0], bl[2]}, b1l[2] = {bl[1], bl[3]};
                #pragma unroll
                for (int mt = 0; mt < 2; mt++) {
                    hmma(acc0[mt][2 * np],     a_hi[mt], b0h);
                    hmma(acc1[mt][2 * np],     a_hi[mt], b0l);
                    hmma(acc1[mt][2 * np],     a_lo[mt], b0h);
                    hmma(acc0[mt][2 * np + 1], a_hi[mt], b1h);
                    hmma(acc1[mt][2 * np + 1], a_hi[mt], b1l);
                    hmma(acc1[mt][2 * np + 1], a_lo[mt], b1h);
                }
            }
        }
        cp_wait0();
        __syncthreads();
    }

    // Epilogue: v = D0 + D1/2048 + bias -> lrelu -> store
    const float inv = 1.0f / 2048.0f;
    #pragma unroll
    for (int mt = 0; mt < 2; mt++) {
        int row = m0 + warp_m * 32 + mt * 16 + (lane >> 2);
        #pragma unroll
        for (int nt = 0; nt < 8; nt++) {
            int col = n0 + warp_n * 64 + nt * 8 + 2 * (lane & 3);
            float bx = bias[col], by = bias[col + 1];
            #pragma unroll
            for (int h = 0; h < 2; h++) {
                int r = row + h * 8;
                if (r >= M) continue;
                float v0 = acc0[mt][nt][2 * h + 0] + acc1[mt][nt][2 * h + 0] * inv + bx;
                float v1 = acc0[mt][nt][2 * h + 1] + acc1[mt][nt][2 * h + 1] * inv + by;
                v0 = v0 > 0.f ? v0 : 0.01f * v0;
                v1 = v1 > 0.f ? v1 : 0.01f * v1;
                if (HALF_OUT) {
                    __half h0 = __float2half_rn(v0);
                    __half h1 = __float2half_rn(v1);
                    __half l0 = __float2half_rn((v0 - __half2float(h0)) * 2048.0f);
                    __half l1 = __float2half_rn((v1 - __half2float(h1)) * 2048.0f);
                    size_t idx = (size_t)r * ldc + col;
                    *reinterpret_cast<__half2*>(Chi + idx) = __halves2half2(h0, h1);
                    *reinterpret_cast<__half2*>(Clo + idx) = __halves2half2(l0, l1);
                } else {
                    size_t idx = (size_t)r * ldc + col;
                    *reinterpret_cast<float2*>(Cf + idx) = make_float2(v0, v1);
                }
            }
        }
    }
}

// ---------------------------------------------------------------------------
// 6) BN column statistics
// ---------------------------------------------------------------------------
__global__ void k_colsum() {
    int col = threadIdx.x;
    float s = 0.f, ss = 0.f;
    for (int r = blockIdx.x; r < NN; r += gridDim.x) {
        float v = g_h2[(size_t)r * DOUT + col];
        s += v;
        ss += v * v;
    }
    atomicAdd(&g_sum[col], s);
    atomicAdd(&g_sumsq[col], ss);
}

__global__ void k_bn_finalize(const float* __restrict__ gamma,
                              const float* __restrict__ beta) {
    int c = threadIdx.x;
    float invn = 1.0f / (float)NN;
    float mean = g_sum[c] * invn;
    float var = g_sumsq[c] * invn - mean * mean;
    float rstd = rsqrtf(var + 1e-5f);
    float sc = gamma[c] * rstd;
    g_scale[c] = sc;
    g_shift[c] = beta[c] - mean * sc;
}

__global__ void k_normalize(float* __restrict__ out) {
    int i = blockIdx.x * blockDim.x + threadIdx.x;
    const int n4 = NN * DOUT / 4;
    if (i >= n4) return;
    int c4 = i & (DOUT / 4 - 1);
    float4 v = reinterpret_cast<const float4*>(g_h2)[i];
    float4 sc = reinterpret_cast<const float4*>(g_scale)[c4];
    float4 sh = reinterpret_cast<const float4*>(g_shift)[c4];
    v.x = v.x * sc.x + sh.x;
    v.y = v.y * sc.y + sh.y;
    v.z = v.z * sc.z + sh.z;
    v.w = v.w * sc.w + sh.w;
    reinterpret_cast<float4*>(out)[i] = v;
}

// ---------------------------------------------------------------------------
extern "C" void kernel_launch(void* const* d_in, const int* in_sizes, int n_in,
                              void* d_out, int out_size) {
    const float* x     = (const float*)d_in[0];
    const int*   ei    = (const int*)d_in[1];
    const float* W1    = (const float*)d_in[2];
    const float* b1    = (const float*)d_in[3];
    const float* W2    = (const float*)d_in[4];
    const float* b2    = (const float*)d_in[5];
    const float* gamma = (const float*)d_in[6];
    const float* beta  = (const float*)d_in[7];
    float* out = (float*)d_out;

    __half *xhi, *xlo, *mhi, *mlo, *w1hi, *w1lo, *w2hi, *w2lo;
    float* h2;
    cudaGetSymbolAddress((void**)&xhi, g_xhi);
    cudaGetSymbolAddress((void**)&xlo, g_xlo);
    cudaGetSymbolAddress((void**)&mhi, g_mhi);
    cudaGetSymbolAddress((void**)&mlo, g_mlo);
    cudaGetSymbolAddress((void**)&w1hi, g_w1hi);
    cudaGetSymbolAddress((void**)&w1lo, g_w1lo);
    cudaGetSymbolAddress((void**)&w2hi, g_w2hi);
    cudaGetSymbolAddress((void**)&w2lo, g_w2lo);
    cudaGetSymbolAddress((void**)&h2, g_h2);

    cudaFuncSetAttribute(k_gemm_mma<true>,
                         cudaFuncAttributeMaxDynamicSharedMemorySize, GEMM_SMEM);
    cudaFuncSetAttribute(k_gemm_mma<false>,
                         cudaFuncAttributeMaxDynamicSharedMemorySize, GEMM_SMEM);

    // 1) h1 = x, zero stats
    k_init<<<(NN * DIN / 4 + 255) / 256, 256>>>(x);
    // 2) scatter-add
    {
        long long tot = (long long)NE * 32;
        k_scatter<<<(int)((tot + 255) / 256), 256>>>(x, ei);
    }
    // 3) splits / weight prep
    k_split_h1<<<(NN * DIN + 255) / 256, 256>>>();
    k_prep_w<<<(DIN * DHID + 255) / 256, 256>>>(W1, w1hi, w1lo, DIN, DHID);
    k_prep_w<<<(DHID * DOUT + 255) / 256, 256>>>(W2, w2hi, w2lo, DHID, DOUT);
    // 4) GEMM1: hmid = lrelu(h1 @ W1 + b1)  -> fp16 hi/lo   [50000x128]@[128x512]
    {
        dim3 grid(DHID / 128, (NN + 127) / 128);
        k_gemm_mma<true><<<grid, 256, GEMM_SMEM>>>(xhi, xlo, w1hi, w1lo, b1,
                                                   mhi, mlo, nullptr, NN, DIN, DHID);
    }
    // 5) GEMM2: h2 = lrelu(hmid @ W2 + b2) -> fp32   [50000x512]@[512x256]
    {
        dim3 grid(DOUT / 128, (NN + 127) / 128);
        k_gemm_mma<false><<<grid, 256, GEMM_SMEM>>>(mhi, mlo, w2hi, w2lo, b2,
                                                    nullptr, nullptr, h2, NN, DHID, DOUT);
    }
    // 6) BN
    k_colsum<<<512, DOUT>>>();
    k_bn_finalize<<<1, DOUT>>>(gamma, beta);
    k_normalize<<<(NN * DOUT / 4 + 255) / 256, 256>>>(out);
}

// round 4
// speedup vs baseline: 1.5458x; 1.0181x over previous
#include <cuda_runtime.h>
#include <cuda_fp16.h>
#include <cstdint>
#include <cstddef>

#define NN 50000
#define NE 800000
#define DIN 128
#define DHID 512
#define DOUT 256

// ---------------------------------------------------------------------------
// Scratch (device globals — no runtime allocation)
// ---------------------------------------------------------------------------
__device__ __half g_xhi[(size_t)NN * DIN];       // (x+agg) split hi
__device__ __half g_xlo[(size_t)NN * DIN];       // (x+agg) split lo (*2048)
__device__ __half g_mhi[(size_t)NN * DHID];      // hmid hi
__device__ __half g_mlo[(size_t)NN * DHID];      // hmid lo (*2048)
__device__ float g_h2[(size_t)NN * DOUT];        // after layer2+act (fp32)
__device__ __half g_w1hi[(size_t)DHID * DIN];    // W1^T hi  [N][K]
__device__ __half g_w1lo[(size_t)DHID * DIN];
__device__ __half g_w2hi[(size_t)DOUT * DHID];   // W2^T hi
__device__ __half g_w2lo[(size_t)DOUT * DHID];
__device__ float g_sum[DOUT];
__device__ float g_sumsq[DOUT];
__device__ float g_scale[DOUT];
__device__ float g_shift[DOUT];
// CSR build
__device__ int g_deg[NN];
__device__ int g_off[NN + 1];
__device__ int g_cur[NN];
__device__ int g_srcs[NE];

// ---------------------------------------------------------------------------
// PTX helpers (compute_100-safe: mma.sync / ldmatrix / cp.async)
// ---------------------------------------------------------------------------
__device__ __forceinline__ uint32_t smem_u32(const void* p) {
    uint32_t a;
    asm("{ .reg .u64 t; cvta.to.shared.u64 t, %1; cvt.u32.u64 %0, t; }"
        : "=r"(a) : "l"(p));
    return a;
}
__device__ __forceinline__ void cp_async16(uint32_t dst, const void* src, bool pred) {
    int sz = pred ? 16 : 0;
    asm volatile("cp.async.cg.shared.global [%0], [%1], 16, %2;"
                 :: "r"(dst), "l"(src), "r"(sz));
}
__device__ __forceinline__ void cp_commit() {
    asm volatile("cp.async.commit_group;" ::: "memory");
}
__device__ __forceinline__ void cp_wait0() {
    asm volatile("cp.async.wait_group 0;" ::: "memory");
}
__device__ __forceinline__ void ldsm_x4(uint32_t* r, uint32_t addr) {
    asm volatile("ldmatrix.sync.aligned.m8n8.x4.shared.b16 {%0,%1,%2,%3}, [%4];"
                 : "=r"(r[0]), "=r"(r[1]), "=r"(r[2]), "=r"(r[3]) : "r"(addr));
}
__device__ __forceinline__ void hmma(float* c, const uint32_t* a, const uint32_t* b) {
    asm volatile(
        "mma.sync.aligned.m16n8k16.row.col.f32.f16.f16.f32 "
        "{%0,%1,%2,%3}, {%4,%5,%6,%7}, {%8,%9}, {%0,%1,%2,%3};"
        : "+f"(c[0]), "+f"(c[1]), "+f"(c[2]), "+f"(c[3])
        : "r"(a[0]), "r"(a[1]), "r"(a[2]), "r"(a[3]), "r"(b[0]), "r"(b[1]));
}

// ---------------------------------------------------------------------------
// 0) zero: degree counters + BN accumulators
// ---------------------------------------------------------------------------
__global__ void k_zero() {
    int i = blockIdx.x * blockDim.x + threadIdx.x;
    if (i < NN) g_deg[i] = 0;
    if (i < DOUT) { g_sum[i] = 0.f; g_sumsq[i] = 0.f; }
}

// ---------------------------------------------------------------------------
// 1) histogram of dst degrees
// ---------------------------------------------------------------------------
__global__ void k_hist(const int* __restrict__ ei) {
    int e = blockIdx.x * blockDim.x + threadIdx.x;
    if (e < NE) atomicAdd(&g_deg[ei[NE + e]], 1);
}

// ---------------------------------------------------------------------------
// 2) exclusive scan over degrees (single block, 1024 threads)
// ---------------------------------------------------------------------------
__global__ void __launch_bounds__(1024) k_scan() {
    __shared__ int bs[1024];
    const int t = threadIdx.x;
    const int SEG = (NN + 1023) / 1024;
    int start = t * SEG;
    int stop = start + SEG < NN ? start + SEG : NN;
    int s = 0;
    for (int i = start; i < stop; i++) s += g_deg[i];
    bs[t] = s;
    __syncthreads();
    // Hillis-Steele inclusive scan
    for (int d = 1; d < 1024; d <<= 1) {
        int u = (t >= d) ? bs[t - d] : 0;
        __syncthreads();
        if (t >= d) bs[t] += u;
        __syncthreads();
    }
    int run = bs[t] - s;  // exclusive prefix
    for (int i = start; i < stop; i++) {
        g_off[i] = run;
        g_cur[i] = run;
        run += g_deg[i];
    }
    if (t == 1023) g_off[NN] = run;
}

// ---------------------------------------------------------------------------
// 3) bucket edges by dst
// ---------------------------------------------------------------------------
__global__ void k_bucket(const int* __restrict__ ei) {
    int e = blockIdx.x * blockDim.x + threadIdx.x;
    if (e >= NE) return;
    int dst = ei[NE + e];
    int pos = atomicAdd(&g_cur[dst], 1);
    g_srcs[pos] = ei[e];
}

// ---------------------------------------------------------------------------
// 4) aggregate: one warp per node. acc = x[dst] + sum x[src]; split hi/lo fp16
// ---------------------------------------------------------------------------
__global__ void __launch_bounds__(256) k_agg(const float* __restrict__ x) {
    int w = (blockIdx.x * blockDim.x + threadIdx.x) >> 5;
    if (w >= NN) return;
    int lane = threadIdx.x & 31;

    float4 acc = reinterpret_cast<const float4*>(x + (size_t)w * DIN)[lane];
    int beg = g_off[w], end = g_off[w + 1];
    for (int base = beg; base < end; base += 32) {
        int n = end - base;
        if (n > 32) n = 32;
        int s = (lane < n) ? g_srcs[base + lane] : 0;
        for (int j = 0; j < n; j++) {
            int src = __shfl_sync(0xffffffffu, s, j);
            float4 v = reinterpret_cast<const float4*>(x + (size_t)src * DIN)[lane];
            acc.x += v.x; acc.y += v.y; acc.z += v.z; acc.w += v.w;
        }
    }
    // split hi/lo
    __half hx = __float2half_rn(acc.x), hy = __float2half_rn(acc.y);
    __half hz = __float2half_rn(acc.z), hw = __float2half_rn(acc.w);
    __half lx = __float2half_rn((acc.x - __half2float(hx)) * 2048.0f);
    __half ly = __float2half_rn((acc.y - __half2float(hy)) * 2048.0f);
    __half lz = __float2half_rn((acc.z - __half2float(hz)) * 2048.0f);
    __half lw = __float2half_rn((acc.w - __half2float(hw)) * 2048.0f);
    size_t idx = (size_t)w * DIN + lane * 4;
    __half2* phi = reinterpret_cast<__half2*>(g_xhi + idx);
    __half2* plo = reinterpret_cast<__half2*>(g_xlo + idx);
    phi[0] = __halves2half2(hx, hy);
    phi[1] = __halves2half2(hz, hw);
    plo[0] = __halves2half2(lx, ly);
    plo[1] = __halves2half2(lz, lw);
}

// ---------------------------------------------------------------------------
// 5) W [K,N] row-major -> W^T [N,K] hi/lo fp16
// ---------------------------------------------------------------------------
__global__ void k_prep_w(const float* __restrict__ W, __half* __restrict__ hi,
                         __half* __restrict__ lo, int K, int N) {
    int i = blockIdx.x * blockDim.x + threadIdx.x;
    if (i >= K * N) return;
    int n = i / K, k = i % K;
    float v = W[(size_t)k * N + n];
    __half h = __float2half_rn(v);
    hi[i] = h;
    lo[i] = __float2half_rn((v - __half2float(h)) * 2048.0f);
}

// ---------------------------------------------------------------------------
// 6) HMMA GEMM:  C[M,N] = lrelu(A @ B^T + bias), split-fp16 3-term
//    CTA tile 128x128, BK=32, 8 warps, double-buffered cp.async.
//    HALF_OUT=false additionally accumulates BN column stats (fused colsum).
// ---------------------------------------------------------------------------
#define ROWB 80
#define MATB (128 * ROWB)
#define STAGEB (4 * MATB)
#define GEMM_SMEM (2 * STAGEB)

template <bool HALF_OUT>
__global__ void __launch_bounds__(256, 1)
k_gemm_mma(const __half* __restrict__ Ahi, const __half* __restrict__ Alo,
           const __half* __restrict__ Bhi, const __half* __restrict__ Blo,
           const float* __restrict__ bias,
           __half* __restrict__ Chi, __half* __restrict__ Clo,
           float* __restrict__ Cf,
           int M, int K, int ldc) {
    extern __shared__ char smem[];
    const uint32_t sb = smem_u32(smem);
    const int tid = threadIdx.x;
    const int wid = tid >> 5;
    const int lane = tid & 31;
    const int warp_m = wid & 3;
    const int warp_n = wid >> 2;
    const int m0 = blockIdx.y * 128;
    const int n0 = blockIdx.x * 128;

    float acc0[2][8][4];
    float acc1[2][8][4];
    #pragma unroll
    for (int a = 0; a < 2; a++)
        #pragma unroll
        for (int b = 0; b < 8; b++)
            #pragma unroll
            for (int c = 0; c < 4; c++) { acc0[a][b][c] = 0.f; acc1[a][b][c] = 0.f; }

    const int nchunks = K >> 5;

    auto load_chunk = [&](int ch, int s) {
        const int k0 = ch << 5;
        const uint32_t stg = sb + s * STAGEB;
        #pragma unroll
        for (int it = 0; it < 2; it++) {
            int idx = tid + it * 256;
            int row = idx >> 2;
            int c = idx & 3;
            uint32_t soff = (uint32_t)(row * ROWB + c * 16);
            int gmr = m0 + row;
            bool okA = gmr < M;
            cp_async16(stg + 0 * MATB + soff, Ahi + (size_t)gmr * K + k0 + c * 8, okA);
            cp_async16(stg + 1 * MATB + soff, Alo + (size_t)gmr * K + k0 + c * 8, okA);
            int gnr = n0 + row;
            cp_async16(stg + 2 * MATB + soff, Bhi + (size_t)gnr * K + k0 + c * 8, true);
            cp_async16(stg + 3 * MATB + soff, Blo + (size_t)gnr * K + k0 + c * 8, true);
        }
        cp_commit();
    };

    load_chunk(0, 0);
    cp_wait0();
    __syncthreads();

    for (int ch = 0; ch < nchunks; ch++) {
        const int s = ch & 1;
        if (ch + 1 < nchunks) load_chunk(ch + 1, s ^ 1);

        const uint32_t stg = sb + s * STAGEB;
        const uint32_t lrow = (uint32_t)(lane & 15);
        const uint32_t lchk = (uint32_t)(lane >> 4);

        #pragma unroll
        for (int ks = 0; ks < 2; ks++) {
            uint32_t a_hi[2][4], a_lo[2][4];
            #pragma unroll
            for (int mt = 0; mt < 2; mt++) {
                uint32_t r = (uint32_t)(warp_m * 32 + mt * 16) + lrow;
                uint32_t addr = stg + r * ROWB + lchk * 16 + ks * 32;
                ldsm_x4(a_hi[mt], addr + 0 * MATB);
                ldsm_x4(a_lo[mt], addr + 1 * MATB);
            }
            #pragma unroll
            for (int np = 0; np < 4; np++) {
                uint32_t bh[4], bl[4];
                uint32_t r = (uint32_t)(warp_n * 64 + np * 16) + lrow;
                uint32_t addr = stg + r * ROWB + lchk * 16 + ks * 32;
                ldsm_x4(bh, addr + 2 * MATB);
                ldsm_x4(bl, addr + 3 * MATB);
                uint32_t b0h[2] = {bh[0], bh[2]}, b1h[2] = {bh[1], bh[3]};
                uint32_t b0l[2] = {bl[0], bl[2]}, b1l[2] = {bl[1], bl[3]};
                #pragma unroll
                for (int mt = 0; mt < 2; mt++) {
                    hmma(acc0[mt][2 * np],     a_hi[mt], b0h);
                    hmma(acc1[mt][2 * np],     a_hi[mt], b0l);
                    hmma(acc1[mt][2 * np],     a_lo[mt], b0h);
                    hmma(acc0[mt][2 * np + 1], a_hi[mt], b1h);
                    hmma(acc1[mt][2 * np + 1], a_hi[mt], b1l);
                    hmma(acc1[mt][2 * np + 1], a_lo[mt], b1h);
                }
            }
        }
        cp_wait0();
        __syncthreads();
    }

    // Epilogue: v = D0 + D1/2048 + bias -> lrelu -> store (+ BN stats if fp32)
    const float inv = 1.0f / 2048.0f;
    float scol[8][2];
    float qcol[8][2];
    #pragma unroll
    for (int nt = 0; nt < 8; nt++) {
        scol[nt][0] = scol[nt][1] = 0.f;
        qcol[nt][0] = qcol[nt][1] = 0.f;
    }

    #pragma unroll
    for (int mt = 0; mt < 2; mt++) {
        int row = m0 + warp_m * 32 + mt * 16 + (lane >> 2);
        #pragma unroll
        for (int nt = 0; nt < 8; nt++) {
            int col = n0 + warp_n * 64 + nt * 8 + 2 * (lane & 3);
            float bx = bias[col], by = bias[col + 1];
            #pragma unroll
            for (int h = 0; h < 2; h++) {
                int r = row + h * 8;
                if (r >= M) continue;
                float v0 = acc0[mt][nt][2 * h + 0] + acc1[mt][nt][2 * h + 0] * inv + bx;
                float v1 = acc0[mt][nt][2 * h + 1] + acc1[mt][nt][2 * h + 1] * inv + by;
                v0 = v0 > 0.f ? v0 : 0.01f * v0;
                v1 = v1 > 0.f ? v1 : 0.01f * v1;
                if (HALF_OUT) {
                    __half h0 = __float2half_rn(v0);
                    __half h1 = __float2half_rn(v1);
                    __half l0 = __float2half_rn((v0 - __half2float(h0)) * 2048.0f);
                    __half l1 = __float2half_rn((v1 - __half2float(h1)) * 2048.0f);
                    size_t idx = (size_t)r * ldc + col;
                    *reinterpret_cast<__half2*>(Chi + idx) = __halves2half2(h0, h1);
                    *reinterpret_cast<__half2*>(Clo + idx) = __halves2half2(l0, l1);
                } else {
                    size_t idx = (size_t)r * ldc + col;
                    *reinterpret_cast<float2*>(Cf + idx) = make_float2(v0, v1);
                    scol[nt][0] += v0; qcol[nt][0] += v0 * v0;
                    scol[nt][1] += v1; qcol[nt][1] += v1 * v1;
                }
            }
        }
    }

    if (!HALF_OUT) {
        // Reduce stats: lanes sharing (lane&3) own the same column pair.
        float* sarr = reinterpret_cast<float*>(smem);
        float* qarr = sarr + 128;
        __syncthreads();
        if (tid < 128) { sarr[tid] = 0.f; qarr[tid] = 0.f; }
        __syncthreads();
        #pragma unroll
        for (int nt = 0; nt < 8; nt++) {
            float s0 = scol[nt][0], s1 = scol[nt][1];
            float q0 = qcol[nt][0], q1 = qcol[nt][1];
            #pragma unroll
            for (int o = 4; o < 32; o <<= 1) {
                s0 += __shfl_xor_sync(0xffffffffu, s0, o);
                s1 += __shfl_xor_sync(0xffffffffu, s1, o);
                q0 += __shfl_xor_sync(0xffffffffu, q0, o);
                q1 += __shfl_xor_sync(0xffffffffu, q1, o);
            }
            if (lane < 4) {
                int c = warp_n * 64 + nt * 8 + 2 * lane;
                atomicAdd(&sarr[c], s0);
                atomicAdd(&sarr[c + 1], s1);
                atomicAdd(&qarr[c], q0);
                atomicAdd(&qarr[c + 1], q1);
            }
        }
        __syncthreads();
        if (tid < 128) {
            atomicAdd(&g_sum[n0 + tid], sarr[tid]);
            atomicAdd(&g_sumsq[n0 + tid], qarr[tid]);
        }
    }
}

// ---------------------------------------------------------------------------
// 7) BN finalize + normalize
// ---------------------------------------------------------------------------
__global__ void k_bn_finalize(const float* __restrict__ gamma,
                              const float* __restrict__ beta) {
    int c = threadIdx.x;
    float invn = 1.0f / (float)NN;
    float mean = g_sum[c] * invn;
    float var = g_sumsq[c] * invn - mean * mean;
    float rstd = rsqrtf(var + 1e-5f);
    float sc = gamma[c] * rstd;
    g_scale[c] = sc;
    g_shift[c] = beta[c] - mean * sc;
}

__global__ void k_normalize(float* __restrict__ out) {
    int i = blockIdx.x * blockDim.x + threadIdx.x;
    const int n4 = NN * DOUT / 4;
    if (i >= n4) return;
    int c4 = i & (DOUT / 4 - 1);
    float4 v = reinterpret_cast<const float4*>(g_h2)[i];
    float4 sc = reinterpret_cast<const float4*>(g_scale)[c4];
    float4 sh = reinterpret_cast<const float4*>(g_shift)[c4];
    v.x = v.x * sc.x + sh.x;
    v.y = v.y * sc.y + sh.y;
    v.z = v.z * sc.z + sh.z;
    v.w = v.w * sc.w + sh.w;
    reinterpret_cast<float4*>(out)[i] = v;
}

// ---------------------------------------------------------------------------
extern "C" void kernel_launch(void* const* d_in, const int* in_sizes, int n_in,
                              void* d_out, int out_size) {
    const float* x     = (const float*)d_in[0];
    const int*   ei    = (const int*)d_in[1];
    const float* W1    = (const float*)d_in[2];
    const float* b1    = (const float*)d_in[3];
    const float* W2    = (const float*)d_in[4];
    const float* b2    = (const float*)d_in[5];
    const float* gamma = (const float*)d_in[6];
    const float* beta  = (const float*)d_in[7];
    float* out = (float*)d_out;

    __half *xhi, *xlo, *mhi, *mlo, *w1hi, *w1lo, *w2hi, *w2lo;
    float* h2;
    cudaGetSymbolAddress((void**)&xhi, g_xhi);
    cudaGetSymbolAddress((void**)&xlo, g_xlo);
    cudaGetSymbolAddress((void**)&mhi, g_mhi);
    cudaGetSymbolAddress((void**)&mlo, g_mlo);
    cudaGetSymbolAddress((void**)&w1hi, g_w1hi);
    cudaGetSymbolAddress((void**)&w1lo, g_w1lo);
    cudaGetSymbolAddress((void**)&w2hi, g_w2hi);
    cudaGetSymbolAddress((void**)&w2lo, g_w2lo);
    cudaGetSymbolAddress((void**)&h2, g_h2);

    cudaFuncSetAttribute(k_gemm_mma<true>,
                         cudaFuncAttributeMaxDynamicSharedMemorySize, GEMM_SMEM);
    cudaFuncSetAttribute(k_gemm_mma<false>,
                         cudaFuncAttributeMaxDynamicSharedMemorySize, GEMM_SMEM);

    // CSR build + aggregate (+fused fp16 split)
    k_zero<<<(NN + 255) / 256, 256>>>();
    k_hist<<<(NE + 255) / 256, 256>>>(ei);
    k_scan<<<1, 1024>>>();
    k_bucket<<<(NE + 255) / 256, 256>>>(ei);
    k_agg<<<(NN * 32 + 255) / 256, 256>>>(x);

    // weight prep
    k_prep_w<<<(DIN * DHID + 255) / 256, 256>>>(W1, w1hi, w1lo, DIN, DHID);
    k_prep_w<<<(DHID * DOUT + 255) / 256, 256>>>(W2, w2hi, w2lo, DHID, DOUT);

    // GEMM1: hmid = lrelu(h1 @ W1 + b1)  -> fp16 hi/lo   [50000x128]@[128x512]
    {
        dim3 grid(DHID / 128, (NN + 127) / 128);
        k_gemm_mma<true><<<grid, 256, GEMM_SMEM>>>(xhi, xlo, w1hi, w1lo, b1,
                                                   mhi, mlo, nullptr, NN, DIN, DHID);
    }
    // GEMM2: h2 = lrelu(hmid @ W2 + b2) -> fp32 (+fused BN stats)
    {
        dim3 grid(DOUT / 128, (NN + 127) / 128);
        k_gemm_mma<false><<<grid, 256, GEMM_SMEM>>>(mhi, mlo, w2hi, w2lo, b2,
                                                    nullptr, nullptr, h2, NN, DHID, DOUT);
    }
    // BN
    k_bn_finalize<<<1, DOUT>>>(gamma, beta);
    k_normalize<<<(NN * DOUT / 4 + 255) / 256, 256>>>(out);
}

// round 5
// speedup vs baseline: 1.6186x; 1.0471x over previous
#include <cuda_runtime.h>
#include <cuda_fp16.h>
#include <cstdint>
#include <cstddef>

#define NN 50000
#define NE 800000
#define DIN 128
#define DHID 512
#define DOUT 256

// ---------------------------------------------------------------------------
// Scratch (device globals — no runtime allocation)
// ---------------------------------------------------------------------------
__device__ __half g_xhi[(size_t)NN * DIN];       // (x+agg) split hi
__device__ __half g_xlo[(size_t)NN * DIN];       // (x+agg) residual (unscaled)
__device__ __half g_mhi[(size_t)NN * DHID];      // hmid hi
__device__ __half g_mlo[(size_t)NN * DHID];      // hmid residual
__device__ float g_h2[(size_t)NN * DOUT];        // after layer2+act (fp32)
__device__ __half g_w1hi[(size_t)DHID * DIN];    // W1^T hi  [N][K]
__device__ __half g_w1lo[(size_t)DHID * DIN];
__device__ __half g_w2hi[(size_t)DOUT * DHID];   // W2^T hi
__device__ __half g_w2lo[(size_t)DOUT * DHID];
__device__ float g_sum[DOUT];
__device__ float g_sumsq[DOUT];
__device__ float g_scale[DOUT];
__device__ float g_shift[DOUT];
// CSR build
__device__ int g_deg[NN];
__device__ int g_off[NN + 1];
__device__ int g_cur[NN];
__device__ int g_srcs[NE];

// ---------------------------------------------------------------------------
// PTX helpers (compute_100-safe: mma.sync / ldmatrix / cp.async)
// ---------------------------------------------------------------------------
__device__ __forceinline__ uint32_t smem_u32(const void* p) {
    uint32_t a;
    asm("{ .reg .u64 t; cvta.to.shared.u64 t, %1; cvt.u32.u64 %0, t; }"
        : "=r"(a) : "l"(p));
    return a;
}
__device__ __forceinline__ void cp_async16(uint32_t dst, const void* src, bool pred) {
    int sz = pred ? 16 : 0;
    asm volatile("cp.async.cg.shared.global [%0], [%1], 16, %2;"
                 :: "r"(dst), "l"(src), "r"(sz));
}
__device__ __forceinline__ void cp_commit() {
    asm volatile("cp.async.commit_group;" ::: "memory");
}
__device__ __forceinline__ void cp_wait0() {
    asm volatile("cp.async.wait_group 0;" ::: "memory");
}
__device__ __forceinline__ void ldsm_x4(uint32_t* r, uint32_t addr) {
    asm volatile("ldmatrix.sync.aligned.m8n8.x4.shared.b16 {%0,%1,%2,%3}, [%4];"
                 : "=r"(r[0]), "=r"(r[1]), "=r"(r[2]), "=r"(r[3]) : "r"(addr));
}
__device__ __forceinline__ void hmma(float* c, const uint32_t* a, const uint32_t* b) {
    asm volatile(
        "mma.sync.aligned.m16n8k16.row.col.f32.f16.f16.f32 "
        "{%0,%1,%2,%3}, {%4,%5,%6,%7}, {%8,%9}, {%0,%1,%2,%3};"
        : "+f"(c[0]), "+f"(c[1]), "+f"(c[2]), "+f"(c[3])
        : "r"(a[0]), "r"(a[1]), "r"(a[2]), "r"(a[3]), "r"(b[0]), "r"(b[1]));
}

// ---------------------------------------------------------------------------
// 0) zero: degree counters + BN accumulators
// ---------------------------------------------------------------------------
__global__ void k_zero() {
    int i = blockIdx.x * blockDim.x + threadIdx.x;
    if (i < NN) g_deg[i] = 0;
    if (i < DOUT) { g_sum[i] = 0.f; g_sumsq[i] = 0.f; }
}

// ---------------------------------------------------------------------------
// 1) histogram of dst degrees
// ---------------------------------------------------------------------------
__global__ void k_hist(const int* __restrict__ ei) {
    int e = blockIdx.x * blockDim.x + threadIdx.x;
    if (e < NE) atomicAdd(&g_deg[ei[NE + e]], 1);
}

// ---------------------------------------------------------------------------
// 2) exclusive scan over degrees (single block, 1024 threads)
// ---------------------------------------------------------------------------
__global__ void __launch_bounds__(1024) k_scan() {
    __shared__ int bs[1024];
    const int t = threadIdx.x;
    const int SEG = (NN + 1023) / 1024;
    int start = t * SEG;
    int stop = start + SEG < NN ? start + SEG : NN;
    int s = 0;
    for (int i = start; i < stop; i++) s += g_deg[i];
    bs[t] = s;
    __syncthreads();
    for (int d = 1; d < 1024; d <<= 1) {
        int u = (t >= d) ? bs[t - d] : 0;
        __syncthreads();
        if (t >= d) bs[t] += u;
        __syncthreads();
    }
    int run = bs[t] - s;
    for (int i = start; i < stop; i++) {
        g_off[i] = run;
        g_cur[i] = run;
        run += g_deg[i];
    }
    if (t == 1023) g_off[NN] = run;
}

// ---------------------------------------------------------------------------
// 3) bucket edges by dst
// ---------------------------------------------------------------------------
__global__ void k_bucket(const int* __restrict__ ei) {
    int e = blockIdx.x * blockDim.x + threadIdx.x;
    if (e >= NE) return;
    int dst = ei[NE + e];
    int pos = atomicAdd(&g_cur[dst], 1);
    g_srcs[pos] = ei[e];
}

// ---------------------------------------------------------------------------
// 4) aggregate: one warp per node. acc = x[dst] + sum x[src]; split hi/lo fp16
// ---------------------------------------------------------------------------
__global__ void __launch_bounds__(256) k_agg(const float* __restrict__ x) {
    int w = (blockIdx.x * blockDim.x + threadIdx.x) >> 5;
    if (w >= NN) return;
    int lane = threadIdx.x & 31;

    float4 acc = reinterpret_cast<const float4*>(x + (size_t)w * DIN)[lane];
    int beg = g_off[w], end = g_off[w + 1];
    for (int base = beg; base < end; base += 32) {
        int n = end - base;
        if (n > 32) n = 32;
        int s = (lane < n) ? g_srcs[base + lane] : 0;
        #pragma unroll 4
        for (int j = 0; j < n; j++) {
            int src = __shfl_sync(0xffffffffu, s, j);
            float4 v = reinterpret_cast<const float4*>(x + (size_t)src * DIN)[lane];
            acc.x += v.x; acc.y += v.y; acc.z += v.z; acc.w += v.w;
        }
    }
    __half hx = __float2half_rn(acc.x), hy = __float2half_rn(acc.y);
    __half hz = __float2half_rn(acc.z), hw = __float2half_rn(acc.w);
    __half lx = __float2half_rn(acc.x - __half2float(hx));
    __half ly = __float2half_rn(acc.y - __half2float(hy));
    __half lz = __float2half_rn(acc.z - __half2float(hz));
    __half lw = __float2half_rn(acc.w - __half2float(hw));
    size_t idx = (size_t)w * DIN + lane * 4;
    __half2* phi = reinterpret_cast<__half2*>(g_xhi + idx);
    __half2* plo = reinterpret_cast<__half2*>(g_xlo + idx);
    phi[0] = __halves2half2(hx, hy);
    phi[1] = __halves2half2(hz, hw);
    plo[0] = __halves2half2(lx, ly);
    plo[1] = __halves2half2(lz, lw);
}

// ---------------------------------------------------------------------------
// 5) W [K,N] row-major -> W^T [N,K] hi/lo fp16 (unscaled residual)
// ---------------------------------------------------------------------------
__global__ void k_prep_w(const float* __restrict__ W, __half* __restrict__ hi,
                         __half* __restrict__ lo, int K, int N) {
    int i = blockIdx.x * blockDim.x + threadIdx.x;
    if (i >= K * N) return;
    int n = i / K, k = i % K;
    float v = W[(size_t)k * N + n];
    __half h = __float2half_rn(v);
    hi[i] = h;
    lo[i] = __float2half_rn(v - __half2float(h));
}

// ---------------------------------------------------------------------------
// 6) HMMA GEMM: C[M,N] = lrelu(A@B^T + bias), split-fp16 3-term SINGLE acc.
//    CTA tile 256x128, BK=32, 8 warps (4m x 2n), warp tile 64x64,
//    double-buffered cp.async. HALF_OUT=false also fuses BN column stats.
// ---------------------------------------------------------------------------
#define ROWB 80
#define AMATB (256 * ROWB)          // 20480
#define BMATB (128 * ROWB)          // 10240
#define STAGEB (2 * AMATB + 2 * BMATB)   // 61440
#define SM_AHI 0
#define SM_ALO AMATB
#define SM_BHI (2 * AMATB)
#define SM_BLO (2 * AMATB + BMATB)
#define GEMM_SMEM (2 * STAGEB)      // 122880

template <bool HALF_OUT>
__global__ void __launch_bounds__(256, 1)
k_gemm_mma(const __half* __restrict__ Ahi, const __half* __restrict__ Alo,
           const __half* __restrict__ Bhi, const __half* __restrict__ Blo,
           const float* __restrict__ bias,
           __half* __restrict__ Chi, __half* __restrict__ Clo,
           float* __restrict__ Cf,
           int M, int K, int ldc) {
    extern __shared__ char smem[];
    const uint32_t sb = smem_u32(smem);
    const int tid = threadIdx.x;
    const int wid = tid >> 5;
    const int lane = tid & 31;
    const int warp_m = wid & 3;      // 4 m-warps of 64 rows
    const int warp_n = wid >> 2;     // 2 n-warps of 64 cols
    const int m0 = blockIdx.y * 256;
    const int n0 = blockIdx.x * 128;

    float acc[4][8][4];
    #pragma unroll
    for (int a = 0; a < 4; a++)
        #pragma unroll
        for (int b = 0; b < 8; b++)
            #pragma unroll
            for (int c = 0; c < 4; c++) acc[a][b][c] = 0.f;

    const int nchunks = K >> 5;

    auto load_chunk = [&](int ch, int s) {
        const int k0 = ch << 5;
        const uint32_t stg = sb + s * STAGEB;
        // A: 256 rows x 64B = 1024 x 16B per matrix (hi+lo)
        #pragma unroll
        for (int it = 0; it < 4; it++) {
            int idx = tid + it * 256;          // 0..1023
            int row = idx >> 2;                // 0..255
            int c = idx & 3;
            uint32_t soff = (uint32_t)(row * ROWB + c * 16);
            int gmr = m0 + row;
            bool okA = gmr < M;
            cp_async16(stg + SM_AHI + soff, Ahi + (size_t)gmr * K + k0 + c * 8, okA);
            cp_async16(stg + SM_ALO + soff, Alo + (size_t)gmr * K + k0 + c * 8, okA);
        }
        // B: 128 rows x 64B = 512 x 16B per matrix (hi+lo)
        #pragma unroll
        for (int it = 0; it < 2; it++) {
            int idx = tid + it * 256;          // 0..511
            int row = idx >> 2;                // 0..127
            int c = idx & 3;
            uint32_t soff = (uint32_t)(row * ROWB + c * 16);
            int gnr = n0 + row;
            cp_async16(stg + SM_BHI + soff, Bhi + (size_t)gnr * K + k0 + c * 8, true);
            cp_async16(stg + SM_BLO + soff, Blo + (size_t)gnr * K + k0 + c * 8, true);
        }
        cp_commit();
    };

    load_chunk(0, 0);
    cp_wait0();
    __syncthreads();

    for (int ch = 0; ch < nchunks; ch++) {
        const int s = ch & 1;
        if (ch + 1 < nchunks) load_chunk(ch + 1, s ^ 1);

        const uint32_t stg = sb + s * STAGEB;
        const uint32_t lrow = (uint32_t)(lane & 15);
        const uint32_t lchk = (uint32_t)(lane >> 4);

        #pragma unroll
        for (int ks = 0; ks < 2; ks++) {
            uint32_t a_hi[4][4], a_lo[4][4];
            #pragma unroll
            for (int mt = 0; mt < 4; mt++) {
                uint32_t r = (uint32_t)(warp_m * 64 + mt * 16) + lrow;
                uint32_t addr = stg + r * ROWB + lchk * 16 + ks * 32;
                ldsm_x4(a_hi[mt], addr + SM_AHI);
                ldsm_x4(a_lo[mt], addr + SM_ALO);
            }
            #pragma unroll
            for (int np = 0; np < 4; np++) {
                uint32_t bh[4], bl[4];
                uint32_t r = (uint32_t)(warp_n * 64 + np * 16) + lrow;
                uint32_t addr = stg + r * ROWB + lchk * 16 + ks * 32;
                ldsm_x4(bh, addr + SM_BHI);
                ldsm_x4(bl, addr + SM_BLO);
                uint32_t b0h[2] = {bh[0], bh[2]}, b1h[2] = {bh[1], bh[3]};
                uint32_t b0l[2] = {bl[0], bl[2]}, b1l[2] = {bl[1], bl[3]};
                #pragma unroll
                for (int mt = 0; mt < 4; mt++) {
                    hmma(acc[mt][2 * np],     a_hi[mt], b0h);
                    hmma(acc[mt][2 * np],     a_hi[mt], b0l);
                    hmma(acc[mt][2 * np],     a_lo[mt], b0h);
                    hmma(acc[mt][2 * np + 1], a_hi[mt], b1h);
                    hmma(acc[mt][2 * np + 1], a_hi[mt], b1l);
                    hmma(acc[mt][2 * np + 1], a_lo[mt], b1h);
                }
            }
        }
        cp_wait0();
        __syncthreads();
    }

    // Epilogue: v = acc + bias -> lrelu -> store (+ BN stats if fp32)
    float scol[8][2];
    float qcol[8][2];
    #pragma unroll
    for (int nt = 0; nt < 8; nt++) {
        scol[nt][0] = scol[nt][1] = 0.f;
        qcol[nt][0] = qcol[nt][1] = 0.f;
    }

    #pragma unroll
    for (int mt = 0; mt < 4; mt++) {
        int row = m0 + warp_m * 64 + mt * 16 + (lane >> 2);
        #pragma unroll
        for (int nt = 0; nt < 8; nt++) {
            int col = n0 + warp_n * 64 + nt * 8 + 2 * (lane & 3);
            float bx = bias[col], by = bias[col + 1];
            #pragma unroll
            for (int h = 0; h < 2; h++) {
                int r = row + h * 8;
                if (r >= M) continue;
                float v0 = acc[mt][nt][2 * h + 0] + bx;
                float v1 = acc[mt][nt][2 * h + 1] + by;
                v0 = v0 > 0.f ? v0 : 0.01f * v0;
                v1 = v1 > 0.f ? v1 : 0.01f * v1;
                if (HALF_OUT) {
                    __half h0 = __float2half_rn(v0);
                    __half h1 = __float2half_rn(v1);
                    __half l0 = __float2half_rn(v0 - __half2float(h0));
                    __half l1 = __float2half_rn(v1 - __half2float(h1));
                    size_t idx = (size_t)r * ldc + col;
                    *reinterpret_cast<__half2*>(Chi + idx) = __halves2half2(h0, h1);
                    *reinterpret_cast<__half2*>(Clo + idx) = __halves2half2(l0, l1);
                } else {
                    size_t idx = (size_t)r * ldc + col;
                    *reinterpret_cast<float2*>(Cf + idx) = make_float2(v0, v1);
                    scol[nt][0] += v0; qcol[nt][0] += v0 * v0;
                    scol[nt][1] += v1; qcol[nt][1] += v1 * v1;
                }
            }
        }
    }

    if (!HALF_OUT) {
        float* sarr = reinterpret_cast<float*>(smem);
        float* qarr = sarr + 128;
        __syncthreads();
        if (tid < 128) { sarr[tid] = 0.f; qarr[tid] = 0.f; }
        __syncthreads();
        #pragma unroll
        for (int nt = 0; nt < 8; nt++) {
            float s0 = scol[nt][0], s1 = scol[nt][1];
            float q0 = qcol[nt][0], q1 = qcol[nt][1];
            #pragma unroll
            for (int o = 4; o < 32; o <<= 1) {
                s0 += __shfl_xor_sync(0xffffffffu, s0, o);
                s1 += __shfl_xor_sync(0xffffffffu, s1, o);
                q0 += __shfl_xor_sync(0xffffffffu, q0, o);
                q1 += __shfl_xor_sync(0xffffffffu, q1, o);
            }
            if (lane < 4) {
                int c = warp_n * 64 + nt * 8 + 2 * lane;
                atomicAdd(&sarr[c], s0);
                atomicAdd(&sarr[c + 1], s1);
                atomicAdd(&qarr[c], q0);
                atomicAdd(&qarr[c + 1], q1);
            }
        }
        __syncthreads();
        if (tid < 128) {
            atomicAdd(&g_sum[n0 + tid], sarr[tid]);
            atomicAdd(&g_sumsq[n0 + tid], qarr[tid]);
        }
    }
}

// ---------------------------------------------------------------------------
// 7) BN finalize + normalize
// ---------------------------------------------------------------------------
__global__ void k_bn_finalize(const float* __restrict__ gamma,
                              const float* __restrict__ beta) {
    int c = threadIdx.x;
    float invn = 1.0f / (float)NN;
    float mean = g_sum[c] * invn;
    float var = g_sumsq[c] * invn - mean * mean;
    float rstd = rsqrtf(var + 1e-5f);
    float sc = gamma[c] * rstd;
    g_scale[c] = sc;
    g_shift[c] = beta[c] - mean * sc;
}

__global__ void k_normalize(float* __restrict__ out) {
    int i = blockIdx.x * blockDim.x + threadIdx.x;
    const int n4 = NN * DOUT / 4;
    if (i >= n4) return;
    int c4 = i & (DOUT / 4 - 1);
    float4 v = reinterpret_cast<const float4*>(g_h2)[i];
    float4 sc = reinterpret_cast<const float4*>(g_scale)[c4];
    float4 sh = reinterpret_cast<const float4*>(g_shift)[c4];
    v.x = v.x * sc.x + sh.x;
    v.y = v.y * sc.y + sh.y;
    v.z = v.z * sc.z + sh.z;
    v.w = v.w * sc.w + sh.w;
    reinterpret_cast<float4*>(out)[i] = v;
}

// ---------------------------------------------------------------------------
extern "C" void kernel_launch(void* const* d_in, const int* in_sizes, int n_in,
                              void* d_out, int out_size) {
    const float* x     = (const float*)d_in[0];
    const int*   ei    = (const int*)d_in[1];
    const float* W1    = (const float*)d_in[2];
    const float* b1    = (const float*)d_in[3];
    const float* W2    = (const float*)d_in[4];
    const float* b2    = (const float*)d_in[5];
    const float* gamma = (const float*)d_in[6];
    const float* beta  = (const float*)d_in[7];
    float* out = (float*)d_out;

    __half *xhi, *xlo, *mhi, *mlo, *w1hi, *w1lo, *w2hi, *w2lo;
    float* h2;
    cudaGetSymbolAddress((void**)&xhi, g_xhi);
    cudaGetSymbolAddress((void**)&xlo, g_xlo);
    cudaGetSymbolAddress((void**)&mhi, g_mhi);
    cudaGetSymbolAddress((void**)&mlo, g_mlo);
    cudaGetSymbolAddress((void**)&w1hi, g_w1hi);
    cudaGetSymbolAddress((void**)&w1lo, g_w1lo);
    cudaGetSymbolAddress((void**)&w2hi, g_w2hi);
    cudaGetSymbolAddress((void**)&w2lo, g_w2lo);
    cudaGetSymbolAddress((void**)&h2, g_h2);

    cudaFuncSetAttribute(k_gemm_mma<true>,
                         cudaFuncAttributeMaxDynamicSharedMemorySize, GEMM_SMEM);
    cudaFuncSetAttribute(k_gemm_mma<false>,
                         cudaFuncAttributeMaxDynamicSharedMemorySize, GEMM_SMEM);

    // CSR build + aggregate (+fused fp16 split)
    k_zero<<<(NN + 255) / 256, 256>>>();
    k_hist<<<(NE + 255) / 256, 256>>>(ei);
    k_scan<<<1, 1024>>>();
    k_bucket<<<(NE + 255) / 256, 256>>>(ei);
    k_agg<<<(NN * 32 + 255) / 256, 256>>>(x);

    // weight prep
    k_prep_w<<<(DIN * DHID + 255) / 256, 256>>>(W1, w1hi, w1lo, DIN, DHID);
    k_prep_w<<<(DHID * DOUT + 255) / 256, 256>>>(W2, w2hi, w2lo, DHID, DOUT);

    // GEMM1: hmid = lrelu(h1 @ W1 + b1)  -> fp16 hi/lo   [50000x128]@[128x512]
    {
        dim3 grid(DHID / 128, (NN + 255) / 256);
        k_gemm_mma<true><<<grid, 256, GEMM_SMEM>>>(xhi, xlo, w1hi, w1lo, b1,
                                                   mhi, mlo, nullptr, NN, DIN, DHID);
    }
    // GEMM2: h2 = lrelu(hmid @ W2 + b2) -> fp32 (+fused BN stats)
    {
        dim3 grid(DOUT / 128, (NN + 255) / 256);
        k_gemm_mma<false><<<grid, 256, GEMM_SMEM>>>(mhi, mlo, w2hi, w2lo, b2,
                                                    nullptr, nullptr, h2, NN, DHID, DOUT);
    }
    // BN
    k_bn_finalize<<<1, DOUT>>>(gamma, beta);
    k_normalize<<<(NN * DOUT / 4 + 255) / 256, 256>>>(out);
}

// round 6
// speedup vs baseline: 1.7781x; 1.0985x over previous
#include <cuda_runtime.h>
#include <cuda_fp16.h>
#include <cstdint>
#include <cstddef>

#define NN 50000
#define NE 800000
#define DIN 128
#define DHID 512
#define DOUT 256

// ---------------------------------------------------------------------------
// Scratch (device globals — no runtime allocation)
// ---------------------------------------------------------------------------
__device__ __half g_xhi[(size_t)NN * DIN];       // (x+agg) split hi
__device__ __half g_xlo[(size_t)NN * DIN];       // (x+agg) residual (unscaled)
__device__ __half g_mhi[(size_t)NN * DHID];      // hmid hi
__device__ __half g_mlo[(size_t)NN * DHID];      // hmid residual
__device__ float g_h2[(size_t)NN * DOUT];        // after layer2+act (fp32)
__device__ __half g_w1hi[(size_t)DHID * DIN];    // W1^T hi  [N][K]
__device__ __half g_w1lo[(size_t)DHID * DIN];
__device__ __half g_w2hi[(size_t)DOUT * DHID];   // W2^T hi
__device__ __half g_w2lo[(size_t)DOUT * DHID];
__device__ float g_sum[DOUT];
__device__ float g_sumsq[DOUT];
__device__ float g_scale[DOUT];
__device__ float g_shift[DOUT];
// CSR build
__device__ int g_deg[NN];
__device__ int g_off[NN + 1];
__device__ int g_cur[NN];
__device__ int g_srcs[NE];

// ---------------------------------------------------------------------------
// PTX helpers (compute_100-safe: mma.sync / ldmatrix / cp.async)
// ---------------------------------------------------------------------------
__device__ __forceinline__ uint32_t smem_u32(const void* p) {
    uint32_t a;
    asm("{ .reg .u64 t; cvta.to.shared.u64 t, %1; cvt.u32.u64 %0, t; }"
        : "=r"(a) : "l"(p));
    return a;
}
__device__ __forceinline__ void cp_async16(uint32_t dst, const void* src, bool pred) {
    int sz = pred ? 16 : 0;
    asm volatile("cp.async.cg.shared.global [%0], [%1], 16, %2;"
                 :: "r"(dst), "l"(src), "r"(sz));
}
__device__ __forceinline__ void cp_commit() {
    asm volatile("cp.async.commit_group;" ::: "memory");
}
__device__ __forceinline__ void cp_wait0() {
    asm volatile("cp.async.wait_group 0;" ::: "memory");
}
__device__ __forceinline__ void ldsm_x4(uint32_t* r, uint32_t addr) {
    asm volatile("ldmatrix.sync.aligned.m8n8.x4.shared.b16 {%0,%1,%2,%3}, [%4];"
                 : "=r"(r[0]), "=r"(r[1]), "=r"(r[2]), "=r"(r[3]) : "r"(addr));
}
__device__ __forceinline__ void hmma(float* c, const uint32_t* a, const uint32_t* b) {
    asm volatile(
        "mma.sync.aligned.m16n8k16.row.col.f32.f16.f16.f32 "
        "{%0,%1,%2,%3}, {%4,%5,%6,%7}, {%8,%9}, {%0,%1,%2,%3};"
        : "+f"(c[0]), "+f"(c[1]), "+f"(c[2]), "+f"(c[3])
        : "r"(a[0]), "r"(a[1]), "r"(a[2]), "r"(a[3]), "r"(b[0]), "r"(b[1]));
}

// ---------------------------------------------------------------------------
// 0) zero: degree counters + BN accumulators
// ---------------------------------------------------------------------------
__global__ void k_zero() {
    int i = blockIdx.x * blockDim.x + threadIdx.x;
    if (i < NN) g_deg[i] = 0;
    if (i < DOUT) { g_sum[i] = 0.f; g_sumsq[i] = 0.f; }
}

// ---------------------------------------------------------------------------
// 1) histogram of dst degrees
// ---------------------------------------------------------------------------
__global__ void k_hist(const int* __restrict__ ei) {
    int e = blockIdx.x * blockDim.x + threadIdx.x;
    if (e < NE) atomicAdd(&g_deg[ei[NE + e]], 1);
}

// ---------------------------------------------------------------------------
// 2) exclusive scan over degrees (single block, 1024 threads)
// ---------------------------------------------------------------------------
__global__ void __launch_bounds__(1024) k_scan() {
    __shared__ int bs[1024];
    const int t = threadIdx.x;
    const int SEG = (NN + 1023) / 1024;
    int start = t * SEG;
    int stop = start + SEG < NN ? start + SEG : NN;
    int s = 0;
    for (int i = start; i < stop; i++) s += g_deg[i];
    bs[t] = s;
    __syncthreads();
    for (int d = 1; d < 1024; d <<= 1) {
        int u = (t >= d) ? bs[t - d] : 0;
        __syncthreads();
        if (t >= d) bs[t] += u;
        __syncthreads();
    }
    int run = bs[t] - s;
    for (int i = start; i < stop; i++) {
        g_off[i] = run;
        g_cur[i] = run;
        run += g_deg[i];
    }
    if (t == 1023) g_off[NN] = run;
}

// ---------------------------------------------------------------------------
// 3) bucket edges by dst
// ---------------------------------------------------------------------------
__global__ void k_bucket(const int* __restrict__ ei) {
    int e = blockIdx.x * blockDim.x + threadIdx.x;
    if (e >= NE) return;
    int dst = ei[NE + e];
    int pos = atomicAdd(&g_cur[dst], 1);
    g_srcs[pos] = ei[e];
}

// ---------------------------------------------------------------------------
// 4) aggregate: one warp per node. acc = x[dst] + sum x[src]; split hi/lo fp16
// ---------------------------------------------------------------------------
__global__ void __launch_bounds__(256) k_agg(const float* __restrict__ x) {
    int w = (blockIdx.x * blockDim.x + threadIdx.x) >> 5;
    if (w >= NN) return;
    int lane = threadIdx.x & 31;

    float4 acc = reinterpret_cast<const float4*>(x + (size_t)w * DIN)[lane];
    int beg = g_off[w], end = g_off[w + 1];
    for (int base = beg; base < end; base += 32) {
        int n = end - base;
        if (n > 32) n = 32;
        int s = (lane < n) ? g_srcs[base + lane] : 0;
        #pragma unroll 4
        for (int j = 0; j < n; j++) {
            int src = __shfl_sync(0xffffffffu, s, j);
            float4 v = reinterpret_cast<const float4*>(x + (size_t)src * DIN)[lane];
            acc.x += v.x; acc.y += v.y; acc.z += v.z; acc.w += v.w;
        }
    }
    __half hx = __float2half_rn(acc.x), hy = __float2half_rn(acc.y);
    __half hz = __float2half_rn(acc.z), hw = __float2half_rn(acc.w);
    __half lx = __float2half_rn(acc.x - __half2float(hx));
    __half ly = __float2half_rn(acc.y - __half2float(hy));
    __half lz = __float2half_rn(acc.z - __half2float(hz));
    __half lw = __float2half_rn(acc.w - __half2float(hw));
    size_t idx = (size_t)w * DIN + lane * 4;
    __half2* phi = reinterpret_cast<__half2*>(g_xhi + idx);
    __half2* plo = reinterpret_cast<__half2*>(g_xlo + idx);
    phi[0] = __halves2half2(hx, hy);
    phi[1] = __halves2half2(hz, hw);
    plo[0] = __halves2half2(lx, ly);
    plo[1] = __halves2half2(lz, lw);
}

// ---------------------------------------------------------------------------
// 5) W [K,N] row-major -> W^T [N,K] hi/lo fp16 (unscaled residual)
// ---------------------------------------------------------------------------
__global__ void k_prep_w(const float* __restrict__ W, __half* __restrict__ hi,
                         __half* __restrict__ lo, int K, int N) {
    int i = blockIdx.x * blockDim.x + threadIdx.x;
    if (i >= K * N) return;
    int n = i / K, k = i % K;
    float v = W[(size_t)k * N + n];
    __half h = __float2half_rn(v);
    hi[i] = h;
    lo[i] = __float2half_rn(v - __half2float(h));
}

// ---------------------------------------------------------------------------
// 6) HMMA GEMM: C[M,N] = lrelu(A@B^T + bias), split-fp16 3-term single acc.
//    CTA tile 128x128, BK=32, 8 warps (4m x 2n), warp tile 32x64,
//    double-buffered cp.async, 2 CTAs/SM. HALF_OUT=false fuses BN stats.
// ---------------------------------------------------------------------------
#define ROWB 80
#define MATB (128 * ROWB)            // 10240
#define STAGEB (4 * MATB)            // 40960: Ahi,Alo,Bhi,Blo
#define SM_AHI 0
#define SM_ALO MATB
#define SM_BHI (2 * MATB)
#define SM_BLO (3 * MATB)
#define GEMM_SMEM (2 * STAGEB)       // 81920 -> 2 CTAs/SM (163840 < 228KB)

template <bool HALF_OUT>
__global__ void __launch_bounds__(256, 2)
k_gemm_mma(const __half* __restrict__ Ahi, const __half* __restrict__ Alo,
           const __half* __restrict__ Bhi, const __half* __restrict__ Blo,
           const float* __restrict__ bias,
           __half* __restrict__ Chi, __half* __restrict__ Clo,
           float* __restrict__ Cf,
           int M, int K, int ldc) {
    extern __shared__ char smem[];
    const uint32_t sb = smem_u32(smem);
    const int tid = threadIdx.x;
    const int wid = tid >> 5;
    const int lane = tid & 31;
    const int warp_m = wid & 3;      // 4 m-warps of 32 rows
    const int warp_n = wid >> 2;     // 2 n-warps of 64 cols
    const int m0 = blockIdx.y * 128;
    const int n0 = blockIdx.x * 128;

    float acc[2][8][4];
    #pragma unroll
    for (int a = 0; a < 2; a++)
        #pragma unroll
        for (int b = 0; b < 8; b++)
            #pragma unroll
            for (int c = 0; c < 4; c++) acc[a][b][c] = 0.f;

    const int nchunks = K >> 5;

    auto load_chunk = [&](int ch, int s) {
        const int k0 = ch << 5;
        const uint32_t stg = sb + s * STAGEB;
        #pragma unroll
        for (int it = 0; it < 2; it++) {
            int idx = tid + it * 256;          // 0..511
            int row = idx >> 2;                // 0..127
            int c = idx & 3;
            uint32_t soff = (uint32_t)(row * ROWB + c * 16);
            int gmr = m0 + row;
            bool okA = gmr < M;
            cp_async16(stg + SM_AHI + soff, Ahi + (size_t)gmr * K + k0 + c * 8, okA);
            cp_async16(stg + SM_ALO + soff, Alo + (size_t)gmr * K + k0 + c * 8, okA);
            int gnr = n0 + row;
            cp_async16(stg + SM_BHI + soff, Bhi + (size_t)gnr * K + k0 + c * 8, true);
            cp_async16(stg + SM_BLO + soff, Blo + (size_t)gnr * K + k0 + c * 8, true);
        }
        cp_commit();
    };

    load_chunk(0, 0);
    cp_wait0();
    __syncthreads();

    for (int ch = 0; ch < nchunks; ch++) {
        const int s = ch & 1;
        if (ch + 1 < nchunks) load_chunk(ch + 1, s ^ 1);

        const uint32_t stg = sb + s * STAGEB;
        const uint32_t lrow = (uint32_t)(lane & 15);
        const uint32_t lchk = (uint32_t)(lane >> 4);

        #pragma unroll
        for (int ks = 0; ks < 2; ks++) {
            uint32_t a_hi[2][4], a_lo[2][4];
            #pragma unroll
            for (int mt = 0; mt < 2; mt++) {
                uint32_t r = (uint32_t)(warp_m * 32 + mt * 16) + lrow;
                uint32_t addr = stg + r * ROWB + lchk * 16 + ks * 32;
                ldsm_x4(a_hi[mt], addr + SM_AHI);
                ldsm_x4(a_lo[mt], addr + SM_ALO);
            }
            #pragma unroll
            for (int np = 0; np < 4; np++) {
                uint32_t bh[4], bl[4];
                uint32_t r = (uint32_t)(warp_n * 64 + np * 16) + lrow;
                uint32_t addr = stg + r * ROWB + lchk * 16 + ks * 32;
                ldsm_x4(bh, addr + SM_BHI);
                ldsm_x4(bl, addr + SM_BLO);
                uint32_t b0h[2] = {bh[0], bh[2]}, b1h[2] = {bh[1], bh[3]};
                uint32_t b0l[2] = {bl[0], bl[2]}, b1l[2] = {bl[1], bl[3]};
                #pragma unroll
                for (int mt = 0; mt < 2; mt++) {
                    hmma(acc[mt][2 * np],     a_hi[mt], b0h);
                    hmma(acc[mt][2 * np],     a_hi[mt], b0l);
                    hmma(acc[mt][2 * np],     a_lo[mt], b0h);
                    hmma(acc[mt][2 * np + 1], a_hi[mt], b1h);
                    hmma(acc[mt][2 * np + 1], a_hi[mt], b1l);
                    hmma(acc[mt][2 * np + 1], a_lo[mt], b1h);
                }
            }
        }
        cp_wait0();
        __syncthreads();
    }

    // Epilogue: v = acc + bias -> lrelu -> store (+ BN stats if fp32)
    float scol[8][2];
    float qcol[8][2];
    #pragma unroll
    for (int nt = 0; nt < 8; nt++) {
        scol[nt][0] = scol[nt][1] = 0.f;
        qcol[nt][0] = qcol[nt][1] = 0.f;
    }

    #pragma unroll
    for (int mt = 0; mt < 2; mt++) {
        int row = m0 + warp_m * 32 + mt * 16 + (lane >> 2);
        #pragma unroll
        for (int nt = 0; nt < 8; nt++) {
            int col = n0 + warp_n * 64 + nt * 8 + 2 * (lane & 3);
            float bx = bias[col], by = bias[col + 1];
            #pragma unroll
            for (int h = 0; h < 2; h++) {
                int r = row + h * 8;
                if (r >= M) continue;
                float v0 = acc[mt][nt][2 * h + 0] + bx;
                float v1 = acc[mt][nt][2 * h + 1] + by;
                v0 = v0 > 0.f ? v0 : 0.01f * v0;
                v1 = v1 > 0.f ? v1 : 0.01f * v1;
                if (HALF_OUT) {
                    __half h0 = __float2half_rn(v0);
                    __half h1 = __float2half_rn(v1);
                    __half l0 = __float2half_rn(v0 - __half2float(h0));
                    __half l1 = __float2half_rn(v1 - __half2float(h1));
                    size_t idx = (size_t)r * ldc + col;
                    *reinterpret_cast<__half2*>(Chi + idx) = __halves2half2(h0, h1);
                    *reinterpret_cast<__half2*>(Clo + idx) = __halves2half2(l0, l1);
                } else {
                    size_t idx = (size_t)r * ldc + col;
                    *reinterpret_cast<float2*>(Cf + idx) = make_float2(v0, v1);
                    scol[nt][0] += v0; qcol[nt][0] += v0 * v0;
                    scol[nt][1] += v1; qcol[nt][1] += v1 * v1;
                }
            }
        }
    }

    if (!HALF_OUT) {
        float* sarr = reinterpret_cast<float*>(smem);
        float* qarr = sarr + 128;
        __syncthreads();
        if (tid < 128) { sarr[tid] = 0.f; qarr[tid] = 0.f; }
        __syncthreads();
        #pragma unroll
        for (int nt = 0; nt < 8; nt++) {
            float s0 = scol[nt][0], s1 = scol[nt][1];
            float q0 = qcol[nt][0], q1 = qcol[nt][1];
            #pragma unroll
            for (int o = 4; o < 32; o <<= 1) {
                s0 += __shfl_xor_sync(0xffffffffu, s0, o);
                s1 += __shfl_xor_sync(0xffffffffu, s1, o);
                q0 += __shfl_xor_sync(0xffffffffu, q0, o);
                q1 += __shfl_xor_sync(0xffffffffu, q1, o);
            }
            if (lane < 4) {
                int c = warp_n * 64 + nt * 8 + 2 * lane;
                atomicAdd(&sarr[c], s0);
                atomicAdd(&sarr[c + 1], s1);
                atomicAdd(&qarr[c], q0);
                atomicAdd(&qarr[c + 1], q1);
            }
        }
        __syncthreads();
        if (tid < 128) {
            atomicAdd(&g_sum[n0 + tid], sarr[tid]);
            atomicAdd(&g_sumsq[n0 + tid], qarr[tid]);
        }
    }
}

// ---------------------------------------------------------------------------
// 7) BN finalize + normalize
// ---------------------------------------------------------------------------
__global__ void k_bn_finalize(const float* __restrict__ gamma,
                              const float* __restrict__ beta) {
    int c = threadIdx.x;
    float invn = 1.0f / (float)NN;
    float mean = g_sum[c] * invn;
    float var = g_sumsq[c] * invn - mean * mean;
    float rstd = rsqrtf(var + 1e-5f);
    float sc = gamma[c] * rstd;
    g_scale[c] = sc;
    g_shift[c] = beta[c] - mean * sc;
}

__global__ void k_normalize(float* __restrict__ out) {
    int i = blockIdx.x * blockDim.x + threadIdx.x;
    const int n4 = NN * DOUT / 4;
    if (i >= n4) return;
    int c4 = i & (DOUT / 4 - 1);
    float4 v = reinterpret_cast<const float4*>(g_h2)[i];
    float4 sc = reinterpret_cast<const float4*>(g_scale)[c4];
    float4 sh = reinterpret_cast<const float4*>(g_shift)[c4];
    v.x = v.x * sc.x + sh.x;
    v.y = v.y * sc.y + sh.y;
    v.z = v.z * sc.z + sh.z;
    v.w = v.w * sc.w + sh.w;
    reinterpret_cast<float4*>(out)[i] = v;
}

// ---------------------------------------------------------------------------
extern "C" void kernel_launch(void* const* d_in, const int* in_sizes, int n_in,
                              void* d_out, int out_size) {
    const float* x     = (const float*)d_in[0];
    const int*   ei    = (const int*)d_in[1];
    const float* W1    = (const float*)d_in[2];
    const float* b1    = (const float*)d_in[3];
    const float* W2    = (const float*)d_in[4];
    const float* b2    = (const float*)d_in[5];
    const float* gamma = (const float*)d_in[6];
    const float* beta  = (const float*)d_in[7];
    float* out = (float*)d_out;

    __half *xhi, *xlo, *mhi, *mlo, *w1hi, *w1lo, *w2hi, *w2lo;
    float* h2;
    cudaGetSymbolAddress((void**)&xhi, g_xhi);
    cudaGetSymbolAddress((void**)&xlo, g_xlo);
    cudaGetSymbolAddress((void**)&mhi, g_mhi);
    cudaGetSymbolAddress((void**)&mlo, g_mlo);
    cudaGetSymbolAddress((void**)&w1hi, g_w1hi);
    cudaGetSymbolAddress((void**)&w1lo, g_w1lo);
    cudaGetSymbolAddress((void**)&w2hi, g_w2hi);
    cudaGetSymbolAddress((void**)&w2lo, g_w2lo);
    cudaGetSymbolAddress((void**)&h2, g_h2);

    cudaFuncSetAttribute(k_gemm_mma<true>,
                         cudaFuncAttributeMaxDynamicSharedMemorySize, GEMM_SMEM);
    cudaFuncSetAttribute(k_gemm_mma<false>,
                         cudaFuncAttributeMaxDynamicSharedMemorySize, GEMM_SMEM);

    // CSR build + aggregate (+fused fp16 split)
    k_zero<<<(NN + 255) / 256, 256>>>();
    k_hist<<<(NE + 255) / 256, 256>>>(ei);
    k_scan<<<1, 1024>>>();
    k_bucket<<<(NE + 255) / 256, 256>>>(ei);
    k_agg<<<(NN * 32 + 255) / 256, 256>>>(x);

    // weight prep
    k_prep_w<<<(DIN * DHID + 255) / 256, 256>>>(W1, w1hi, w1lo, DIN, DHID);
    k_prep_w<<<(DHID * DOUT + 255) / 256, 256>>>(W2, w2hi, w2lo, DHID, DOUT);

    // GEMM1: hmid = lrelu(h1 @ W1 + b1)  -> fp16 hi/lo   [50000x128]@[128x512]
    {
        dim3 grid(DHID / 128, (NN + 127) / 128);
        k_gemm_mma<true><<<grid, 256, GEMM_SMEM>>>(xhi, xlo, w1hi, w1lo, b1,
                                                   mhi, mlo, nullptr, NN, DIN, DHID);
    }
    // GEMM2: h2 = lrelu(hmid @ W2 + b2) -> fp32 (+fused BN stats)
    {
        dim3 grid(DOUT / 128, (NN + 127) / 128);
        k_gemm_mma<false><<<grid, 256, GEMM_SMEM>>>(mhi, mlo, w2hi, w2lo, b2,
                                                    nullptr, nullptr, h2, NN, DHID, DOUT);
    }
    // BN
    k_bn_finalize<<<1, DOUT>>>(gamma, beta);
    k_normalize<<<(NN * DOUT / 4 + 255) / 256, 256>>>(out);
}

// round 7
// speedup vs baseline: 2.0551x; 1.1558x over previous
#include <cuda_runtime.h>
#include <cuda_fp16.h>
#include <cstdint>
#include <cstddef>

#define NN 50000
#define NE 800000
#define DIN 128
#define DHID 512
#define DOUT 256

// ---------------------------------------------------------------------------
// Scratch (device globals — no runtime allocation)
// ---------------------------------------------------------------------------
__device__ __half g_xhi[(size_t)NN * DIN];       // (x+agg) split hi
__device__ __half g_xlo[(size_t)NN * DIN];       // (x+agg) residual (unscaled)
__device__ __half g_mhi[(size_t)NN * DHID];      // hmid hi
__device__ __half g_mlo[(size_t)NN * DHID];      // hmid residual
__device__ float g_h2[(size_t)NN * DOUT];        // after layer2+act (fp32)
__device__ __half g_w1hi[(size_t)DHID * DIN];    // W1^T hi  [N][K]
__device__ __half g_w2hi[(size_t)DOUT * DHID];   // W2^T hi
__device__ float g_sum[DOUT];
__device__ float g_sumsq[DOUT];
__device__ float g_scale[DOUT];
__device__ float g_shift[DOUT];
// CSR build
__device__ int g_deg[NN];
__device__ int g_off[NN + 1];
__device__ int g_cur[NN];
__device__ int g_srcs[NE];

// ---------------------------------------------------------------------------
// PTX helpers (compute_100-safe: mma.sync / ldmatrix / cp.async)
// ---------------------------------------------------------------------------
__device__ __forceinline__ uint32_t smem_u32(const void* p) {
    uint32_t a;
    asm("{ .reg .u64 t; cvta.to.shared.u64 t, %1; cvt.u32.u64 %0, t; }"
        : "=r"(a) : "l"(p));
    return a;
}
__device__ __forceinline__ void cp_async16(uint32_t dst, const void* src, bool pred) {
    int sz = pred ? 16 : 0;
    asm volatile("cp.async.cg.shared.global [%0], [%1], 16, %2;"
                 :: "r"(dst), "l"(src), "r"(sz));
}
__device__ __forceinline__ void cp_commit() {
    asm volatile("cp.async.commit_group;" ::: "memory");
}
__device__ __forceinline__ void cp_wait0() {
    asm volatile("cp.async.wait_group 0;" ::: "memory");
}
__device__ __forceinline__ void cp_wait1() {
    asm volatile("cp.async.wait_group 1;" ::: "memory");
}
__device__ __forceinline__ void ldsm_x4(uint32_t* r, uint32_t addr) {
    asm volatile("ldmatrix.sync.aligned.m8n8.x4.shared.b16 {%0,%1,%2,%3}, [%4];"
                 : "=r"(r[0]), "=r"(r[1]), "=r"(r[2]), "=r"(r[3]) : "r"(addr));
}
__device__ __forceinline__ void hmma(float* c, const uint32_t* a, const uint32_t* b) {
    asm volatile(
        "mma.sync.aligned.m16n8k16.row.col.f32.f16.f16.f32 "
        "{%0,%1,%2,%3}, {%4,%5,%6,%7}, {%8,%9}, {%0,%1,%2,%3};"
        : "+f"(c[0]), "+f"(c[1]), "+f"(c[2]), "+f"(c[3])
        : "r"(a[0]), "r"(a[1]), "r"(a[2]), "r"(a[3]), "r"(b[0]), "r"(b[1]));
}

// ---------------------------------------------------------------------------
// 0) zero: degree counters + BN accumulators
// ---------------------------------------------------------------------------
__global__ void k_zero() {
    int i = blockIdx.x * blockDim.x + threadIdx.x;
    if (i < NN) g_deg[i] = 0;
    if (i < DOUT) { g_sum[i] = 0.f; g_sumsq[i] = 0.f; }
}

// ---------------------------------------------------------------------------
// 1) histogram of dst degrees
// ---------------------------------------------------------------------------
__global__ void k_hist(const int* __restrict__ ei) {
    int e = blockIdx.x * blockDim.x + threadIdx.x;
    if (e < NE) atomicAdd(&g_deg[ei[NE + e]], 1);
}

// ---------------------------------------------------------------------------
// 2) exclusive scan over degrees (single block, 1024 threads)
// ---------------------------------------------------------------------------
__global__ void __launch_bounds__(1024) k_scan() {
    __shared__ int bs[1024];
    const int t = threadIdx.x;
    const int SEG = (NN + 1023) / 1024;
    int start = t * SEG;
    int stop = start + SEG < NN ? start + SEG : NN;
    int s = 0;
    for (int i = start; i < stop; i++) s += g_deg[i];
    bs[t] = s;
    __syncthreads();
    for (int d = 1; d < 1024; d <<= 1) {
        int u = (t >= d) ? bs[t - d] : 0;
        __syncthreads();
        if (t >= d) bs[t] += u;
        __syncthreads();
    }
    int run = bs[t] - s;
    for (int i = start; i < stop; i++) {
        g_off[i] = run;
        g_cur[i] = run;
        run += g_deg[i];
    }
    if (t == 1023) g_off[NN] = run;
}

// ---------------------------------------------------------------------------
// 3) bucket edges by dst
// ---------------------------------------------------------------------------
__global__ void k_bucket(const int* __restrict__ ei) {
    int e = blockIdx.x * blockDim.x + threadIdx.x;
    if (e >= NE) return;
    int dst = ei[NE + e];
    int pos = atomicAdd(&g_cur[dst], 1);
    g_srcs[pos] = ei[e];
}

// ---------------------------------------------------------------------------
// 4) aggregate: one warp per node. acc = x[dst] + sum x[src]; split hi/lo fp16
// ---------------------------------------------------------------------------
__global__ void __launch_bounds__(256) k_agg(const float* __restrict__ x) {
    int w = (blockIdx.x * blockDim.x + threadIdx.x) >> 5;
    if (w >= NN) return;
    int lane = threadIdx.x & 31;

    float4 acc = reinterpret_cast<const float4*>(x + (size_t)w * DIN)[lane];
    int beg = g_off[w], end = g_off[w + 1];
    for (int base = beg; base < end; base += 32) {
        int n = end - base;
        if (n > 32) n = 32;
        int s = (lane < n) ? g_srcs[base + lane] : 0;
        #pragma unroll 4
        for (int j = 0; j < n; j++) {
            int src = __shfl_sync(0xffffffffu, s, j);
            float4 v = reinterpret_cast<const float4*>(x + (size_t)src * DIN)[lane];
            acc.x += v.x; acc.y += v.y; acc.z += v.z; acc.w += v.w;
        }
    }
    __half hx = __float2half_rn(acc.x), hy = __float2half_rn(acc.y);
    __half hz = __float2half_rn(acc.z), hw = __float2half_rn(acc.w);
    __half lx = __float2half_rn(acc.x - __half2float(hx));
    __half ly = __float2half_rn(acc.y - __half2float(hy));
    __half lz = __float2half_rn(acc.z - __half2float(hz));
    __half lw = __float2half_rn(acc.w - __half2float(hw));
    size_t idx = (size_t)w * DIN + lane * 4;
    __half2* phi = reinterpret_cast<__half2*>(g_xhi + idx);
    __half2* plo = reinterpret_cast<__half2*>(g_xlo + idx);
    phi[0] = __halves2half2(hx, hy);
    phi[1] = __halves2half2(hz, hw);
    plo[0] = __halves2half2(lx, ly);
    plo[1] = __halves2half2(lz, lw);
}

// ---------------------------------------------------------------------------
// 5) W [K,N] row-major -> W^T [N,K] fp16 (hi only)
// ---------------------------------------------------------------------------
__global__ void k_prep_w(const float* __restrict__ W, __half* __restrict__ hi,
                         int K, int N) {
    int i = blockIdx.x * blockDim.x + threadIdx.x;
    if (i >= K * N) return;
    int n = i / K, k = i % K;
    hi[i] = __float2half_rn(W[(size_t)k * N + n]);
}

// ---------------------------------------------------------------------------
// 6) HMMA GEMM: C[M,N] = lrelu(A@B^T + bias), split-A 2-term scheme:
//    D = Ahi·B + Alo·B.  CTA tile 128x128, BK=32, 8 warps (4m x 2n),
//    3-stage cp.async ring (wait_group 1), 2 CTAs/SM.
//    HALF_OUT=false fuses BN column stats.
// ---------------------------------------------------------------------------
#define ROWB 80
#define MATB (128 * ROWB)            // 10240
#define STAGEB (3 * MATB)            // 30720: Ahi, Alo, Bhi
#define SM_AHI 0
#define SM_ALO MATB
#define SM_BHI (2 * MATB)
#define NSTAGE 3
#define GEMM_SMEM (NSTAGE * STAGEB)  // 92160 -> 2 CTAs/SM (184320 < 228KB)

template <bool HALF_OUT>
__global__ void __launch_bounds__(256, 2)
k_gemm_mma(const __half* __restrict__ Ahi, const __half* __restrict__ Alo,
           const __half* __restrict__ Bh,
           const float* __restrict__ bias,
           __half* __restrict__ Chi, __half* __restrict__ Clo,
           float* __restrict__ Cf,
           int M, int K, int ldc) {
    extern __shared__ char smem[];
    const uint32_t sb = smem_u32(smem);
    const int tid = threadIdx.x;
    const int wid = tid >> 5;
    const int lane = tid & 31;
    const int warp_m = wid & 3;      // 4 m-warps of 32 rows
    const int warp_n = wid >> 2;     // 2 n-warps of 64 cols
    const int m0 = blockIdx.y * 128;
    const int n0 = blockIdx.x * 128;

    float acc[2][8][4];
    #pragma unroll
    for (int a = 0; a < 2; a++)
        #pragma unroll
        for (int b = 0; b < 8; b++)
            #pragma unroll
            for (int c = 0; c < 4; c++) acc[a][b][c] = 0.f;

    const int nchunks = K >> 5;

    auto load_chunk = [&](int ch) {
        const int k0 = ch << 5;
        const uint32_t stg = sb + (ch % NSTAGE) * STAGEB;
        #pragma unroll
        for (int it = 0; it < 2; it++) {
            int idx = tid + it * 256;          // 0..511
            int row = idx >> 2;                // 0..127
            int c = idx & 3;
            uint32_t soff = (uint32_t)(row * ROWB + c * 16);
            int gmr = m0 + row;
            bool okA = gmr < M;
            cp_async16(stg + SM_AHI + soff, Ahi + (size_t)gmr * K + k0 + c * 8, okA);
            cp_async16(stg + SM_ALO + soff, Alo + (size_t)gmr * K + k0 + c * 8, okA);
            int gnr = n0 + row;
            cp_async16(stg + SM_BHI + soff, Bh + (size_t)gnr * K + k0 + c * 8, true);
        }
        cp_commit();
    };

    load_chunk(0);
    if (nchunks > 1) load_chunk(1);

    for (int ch = 0; ch < nchunks; ch++) {
        if (ch + 1 < nchunks) cp_wait1(); else cp_wait0();
        __syncthreads();

        const uint32_t stg = sb + (ch % NSTAGE) * STAGEB;
        const uint32_t lrow = (uint32_t)(lane & 15);
        const uint32_t lchk = (uint32_t)(lane >> 4);

        #pragma unroll
        for (int ks = 0; ks < 2; ks++) {
            uint32_t a_hi[2][4], a_lo[2][4];
            #pragma unroll
            for (int mt = 0; mt < 2; mt++) {
                uint32_t r = (uint32_t)(warp_m * 32 + mt * 16) + lrow;
                uint32_t addr = stg + r * ROWB + lchk * 16 + ks * 32;
                ldsm_x4(a_hi[mt], addr + SM_AHI);
                ldsm_x4(a_lo[mt], addr + SM_ALO);
            }
            #pragma unroll
            for (int np = 0; np < 4; np++) {
                uint32_t bh[4];
                uint32_t r = (uint32_t)(warp_n * 64 + np * 16) + lrow;
                uint32_t addr = stg + r * ROWB + lchk * 16 + ks * 32;
                ldsm_x4(bh, addr + SM_BHI);
                uint32_t b0h[2] = {bh[0], bh[2]}, b1h[2] = {bh[1], bh[3]};
                #pragma unroll
                for (int mt = 0; mt < 2; mt++) {
                    hmma(acc[mt][2 * np],     a_hi[mt], b0h);
                    hmma(acc[mt][2 * np],     a_lo[mt], b0h);
                    hmma(acc[mt][2 * np + 1], a_hi[mt], b1h);
                    hmma(acc[mt][2 * np + 1], a_lo[mt], b1h);
                }
            }
        }
        __syncthreads();
        if (ch + 2 < nchunks) load_chunk(ch + 2);
    }

    // Epilogue: v = acc + bias -> lrelu -> store (+ BN stats if fp32)
    float scol[8][2];
    float qcol[8][2];
    #pragma unroll
    for (int nt = 0; nt < 8; nt++) {
        scol[nt][0] = scol[nt][1] = 0.f;
        qcol[nt][0] = qcol[nt][1] = 0.f;
    }

    #pragma unroll
    for (int mt = 0; mt < 2; mt++) {
        int row = m0 + warp_m * 32 + mt * 16 + (lane >> 2);
        #pragma unroll
        for (int nt = 0; nt < 8; nt++) {
            int col = n0 + warp_n * 64 + nt * 8 + 2 * (lane & 3);
            float bx = bias[col], by = bias[col + 1];
            #pragma unroll
            for (int h = 0; h < 2; h++) {
                int r = row + h * 8;
                if (r >= M) continue;
                float v0 = acc[mt][nt][2 * h + 0] + bx;
                float v1 = acc[mt][nt][2 * h + 1] + by;
                v0 = v0 > 0.f ? v0 : 0.01f * v0;
                v1 = v1 > 0.f ? v1 : 0.01f * v1;
                if (HALF_OUT) {
                    __half h0 = __float2half_rn(v0);
                    __half h1 = __float2half_rn(v1);
                    __half l0 = __float2half_rn(v0 - __half2float(h0));
                    __half l1 = __float2half_rn(v1 - __half2float(h1));
                    size_t idx = (size_t)r * ldc + col;
                    *reinterpret_cast<__half2*>(Chi + idx) = __halves2half2(h0, h1);
                    *reinterpret_cast<__half2*>(Clo + idx) = __halves2half2(l0, l1);
                } else {
                    size_t idx = (size_t)r * ldc + col;
                    *reinterpret_cast<float2*>(Cf + idx) = make_float2(v0, v1);
                    scol[nt][0] += v0; qcol[nt][0] += v0 * v0;
                    scol[nt][1] += v1; qcol[nt][1] += v1 * v1;
                }
            }
        }
    }

    if (!HALF_OUT) {
        float* sarr = reinterpret_cast<float*>(smem);
        float* qarr = sarr + 128;
        __syncthreads();
        if (tid < 128) { sarr[tid] = 0.f; qarr[tid] = 0.f; }
        __syncthreads();
        #pragma unroll
        for (int nt = 0; nt < 8; nt++) {
            float s0 = scol[nt][0], s1 = scol[nt][1];
            float q0 = qcol[nt][0], q1 = qcol[nt][1];
            #pragma unroll
            for (int o = 4; o < 32; o <<= 1) {
                s0 += __shfl_xor_sync(0xffffffffu, s0, o);
                s1 += __shfl_xor_sync(0xffffffffu, s1, o);
                q0 += __shfl_xor_sync(0xffffffffu, q0, o);
                q1 += __shfl_xor_sync(0xffffffffu, q1, o);
            }
            if (lane < 4) {
                int c = warp_n * 64 + nt * 8 + 2 * lane;
                atomicAdd(&sarr[c], s0);
                atomicAdd(&sarr[c + 1], s1);
                atomicAdd(&qarr[c], q0);
                atomicAdd(&qarr[c + 1], q1);
            }
        }
        __syncthreads();
        if (tid < 128) {
            atomicAdd(&g_sum[n0 + tid], sarr[tid]);
            atomicAdd(&g_sumsq[n0 + tid], qarr[tid]);
        }
    }
}

// ---------------------------------------------------------------------------
// 7) BN finalize + normalize
// ---------------------------------------------------------------------------
__global__ void k_bn_finalize(const float* __restrict__ gamma,
                              const float* __restrict__ beta) {
    int c = threadIdx.x;
    float invn = 1.0f / (float)NN;
    float mean = g_sum[c] * invn;
    float var = g_sumsq[c] * invn - mean * mean;
    float rstd = rsqrtf(var + 1e-5f);
    float sc = gamma[c] * rstd;
    g_scale[c] = sc;
    g_shift[c] = beta[c] - mean * sc;
}

__global__ void k_normalize(float* __restrict__ out) {
    int i = blockIdx.x * blockDim.x + threadIdx.x;
    const int n4 = NN * DOUT / 4;
    if (i >= n4) return;
    int c4 = i & (DOUT / 4 - 1);
    float4 v = reinterpret_cast<const float4*>(g_h2)[i];
    float4 sc = reinterpret_cast<const float4*>(g_scale)[c4];
    float4 sh = reinterpret_cast<const float4*>(g_shift)[c4];
    v.x = v.x * sc.x + sh.x;
    v.y = v.y * sc.y + sh.y;
    v.z = v.z * sc.z + sh.z;
    v.w = v.w * sc.w + sh.w;
    reinterpret_cast<float4*>(out)[i] = v;
}

// ---------------------------------------------------------------------------
extern "C" void kernel_launch(void* const* d_in, const int* in_sizes, int n_in,
                              void* d_out, int out_size) {
    const float* x     = (const float*)d_in[0];
    const int*   ei    = (const int*)d_in[1];
    const float* W1    = (const float*)d_in[2];
    const float* b1    = (const float*)d_in[3];
    const float* W2    = (const float*)d_in[4];
    const float* b2    = (const float*)d_in[5];
    const float* gamma = (const float*)d_in[6];
    const float* beta  = (const float*)d_in[7];
    float* out = (float*)d_out;

    __half *xhi, *xlo, *mhi, *mlo, *w1hi, *w2hi;
    float* h2;
    cudaGetSymbolAddress((void**)&xhi, g_xhi);
    cudaGetSymbolAddress((void**)&xlo, g_xlo);
    cudaGetSymbolAddress((void**)&mhi, g_mhi);
    cudaGetSymbolAddress((void**)&mlo, g_mlo);
    cudaGetSymbolAddress((void**)&w1hi, g_w1hi);
    cudaGetSymbolAddress((void**)&w2hi, g_w2hi);
    cudaGetSymbolAddress((void**)&h2, g_h2);

    cudaFuncSetAttribute(k_gemm_mma<true>,
                         cudaFuncAttributeMaxDynamicSharedMemorySize, GEMM_SMEM);
    cudaFuncSetAttribute(k_gemm_mma<false>,
                         cudaFuncAttributeMaxDynamicSharedMemorySize, GEMM_SMEM);

    // CSR build + aggregate (+fused fp16 split)
    k_zero<<<(NN + 255) / 256, 256>>>();
    k_hist<<<(NE + 255) / 256, 256>>>(ei);
    k_scan<<<1, 1024>>>();
    k_bucket<<<(NE + 255) / 256, 256>>>(ei);
    k_agg<<<(NN * 32 + 255) / 256, 256>>>(x);

    // weight prep (fp16, no residual)
    k_prep_w<<<(DIN * DHID + 255) / 256, 256>>>(W1, w1hi, DIN, DHID);
    k_prep_w<<<(DHID * DOUT + 255) / 256, 256>>>(W2, w2hi, DHID, DOUT);

    // GEMM1: hmid = lrelu(h1 @ W1 + b1)  -> fp16 hi/lo   [50000x128]@[128x512]
    {
        dim3 grid(DHID / 128, (NN + 127) / 128);
        k_gemm_mma<true><<<grid, 256, GEMM_SMEM>>>(xhi, xlo, w1hi, b1,
                                                   mhi, mlo, nullptr, NN, DIN, DHID);
    }
    // GEMM2: h2 = lrelu(hmid @ W2 + b2) -> fp32 (+fused BN stats)
    {
        dim3 grid(DOUT / 128, (NN + 127) / 128);
        k_gemm_mma<false><<<grid, 256, GEMM_SMEM>>>(mhi, mlo, w2hi, b2,
                                                    nullptr, nullptr, h2, NN, DHID, DOUT);
    }
    // BN
    k_bn_finalize<<<1, DOUT>>>(gamma, beta);
    k_normalize<<<(NN * DOUT / 4 + 255) / 256, 256>>>(out);
}